// round 13
// baseline (speedup 1.0000x reference)
#include <cuda_runtime.h>
#include <mma.h>
#include <math.h>

using namespace nvcuda;

#define NN 50000
#define EE 400000
#define DD 128
#define CC 8

#define TILE_E 64
#define NTHR 256
#define MS 132   // row stride in floats (132*4 = 528 B, 16B-aligned rows)

typedef unsigned long long ull;

// ---------------- device scratch (no allocations allowed) ----------------
__device__ float g_node_agg[NN * DD];
__device__ float g_coord_sum[NN * CC * 3];
__device__ float g_cnt[NN];
__device__ float g_pcol[NN * 3];
__device__ int   g_csum[NN];
__device__ unsigned int g_maxbits;
__device__ float g_Ah[(NN + 64) * DD];   // +64 rows padding for wmma tile overrun
__device__ float g_Bh[(NN + 64) * DD];

// edge-pre outputs
__device__ float g_rad[EE * 8];
__device__ float g_cdiff[EE * 24];
__device__ int4  g_meta[EE];
__device__ float g_wr[EE];

// packed weights for the small FFMA2 path
__device__ ull g_CW2p[64 * 8];     // c_w2

__device__ __forceinline__ float silu_f(float x) {
    return x * (1.0f / (1.0f + __expf(-x)));
}
__device__ __forceinline__ ull packf2(float lo, float hi) {
    return ((ull)__float_as_uint(hi) << 32) | (ull)__float_as_uint(lo);
}
__device__ __forceinline__ float lo_f(ull p) { return __uint_as_float((unsigned)(p & 0xffffffffull)); }
__device__ __forceinline__ float hi_f(ull p) { return __uint_as_float((unsigned)(p >> 32)); }

#define FMA2(d, a, b, c) asm("fma.rn.f32x2 %0, %1, %2, %3;" : "=l"(d) : "l"(a), "l"(b), "l"(c))

// ---------------- shared wmma helper ----------------
// dst(64x128, dst_stride) = src(64x128, stride MS) @ W(128x128 row-major)
// 8 warps: warp w -> m-tile (w&3), n-tiles [(w>>2)*4, (w>>2)*4+4)
__device__ __forceinline__ void wmma_gemm_64x128x128(const float* __restrict__ src,
                                                     const float* __restrict__ W,
                                                     float* __restrict__ dst,
                                                     int dst_stride,
                                                     int tid) {
    const int w   = tid >> 5;
    const int mt  = w & 3;
    const int nt0 = (w >> 2) * 4;

    wmma::fragment<wmma::accumulator, 16, 16, 8, float> c[4];
#pragma unroll
    for (int j = 0; j < 4; j++) wmma::fill_fragment(c[j], 0.f);

    for (int k = 0; k < 16; k++) {
        wmma::fragment<wmma::matrix_a, 16, 16, 8, wmma::precision::tf32, wmma::row_major> fa;
        wmma::load_matrix_sync(fa, src + (mt * 16) * MS + k * 8, MS);
#pragma unroll
        for (int i = 0; i < fa.num_elements; i++) fa.x[i] = wmma::__float_to_tf32(fa.x[i]);
#pragma unroll
        for (int j = 0; j < 4; j++) {
            wmma::fragment<wmma::matrix_b, 16, 16, 8, wmma::precision::tf32, wmma::row_major> fb;
            wmma::load_matrix_sync(fb, W + (k * 8) * 128 + (nt0 + j) * 16, 128);
#pragma unroll
            for (int i = 0; i < fb.num_elements; i++) fb.x[i] = wmma::__float_to_tf32(fb.x[i]);
            wmma::mma_sync(c[j], fa, fb, c[j]);
        }
    }
#pragma unroll
    for (int j = 0; j < 4; j++)
        wmma::store_matrix_sync(dst + (mt * 16) * dst_stride + (nt0 + j) * 16, c[j],
                                dst_stride, wmma::mem_row_major);
}

// 32-row variant for node_out (unchanged geometry from R12)
__device__ __forceinline__ void wmma_gemm_32x128x128(const float* __restrict__ src,
                                                     const float* __restrict__ W,
                                                     float* __restrict__ dst,
                                                     int dst_stride,
                                                     int tid) {
    const int w   = tid >> 5;
    const int mt  = w & 1;
    const int nt0 = (w >> 1) * 2;

    wmma::fragment<wmma::accumulator, 16, 16, 8, float> c0, c1;
    wmma::fill_fragment(c0, 0.f);
    wmma::fill_fragment(c1, 0.f);

    for (int k = 0; k < 16; k++) {
        wmma::fragment<wmma::matrix_a, 16, 16, 8, wmma::precision::tf32, wmma::row_major> fa;
        wmma::fragment<wmma::matrix_b, 16, 16, 8, wmma::precision::tf32, wmma::row_major> fb0, fb1;
        wmma::load_matrix_sync(fa, src + (mt * 16) * MS + k * 8, MS);
#pragma unroll
        for (int i = 0; i < fa.num_elements; i++) fa.x[i] = wmma::__float_to_tf32(fa.x[i]);
        wmma::load_matrix_sync(fb0, W + (k * 8) * 128 + nt0 * 16, 128);
        wmma::load_matrix_sync(fb1, W + (k * 8) * 128 + (nt0 + 1) * 16, 128);
#pragma unroll
        for (int i = 0; i < fb0.num_elements; i++) fb0.x[i] = wmma::__float_to_tf32(fb0.x[i]);
#pragma unroll
        for (int i = 0; i < fb1.num_elements; i++) fb1.x[i] = wmma::__float_to_tf32(fb1.x[i]);
        wmma::mma_sync(c0, fa, fb0, c0);
        wmma::mma_sync(c1, fa, fb1, c1);
    }
    wmma::store_matrix_sync(dst + (mt * 16) * dst_stride + nt0 * 16, c0, dst_stride, wmma::mem_row_major);
    wmma::store_matrix_sync(dst + (mt * 16) * dst_stride + (nt0 + 1) * 16, c1, dst_stride, wmma::mem_row_major);
}

// ---------------- zero scratch ----------------
__global__ void zero_kernel() {
    long t0 = (long)blockIdx.x * blockDim.x + threadIdx.x;
    long stride = (long)gridDim.x * blockDim.x;
    for (long i = t0; i < (long)NN * DD; i += stride) g_node_agg[i] = 0.f;
    for (long i = t0; i < (long)NN * 24; i += stride) g_coord_sum[i] = 0.f;
    for (long i = t0; i < NN; i += stride) g_cnt[i] = 0.f;
    if (t0 == 0) g_maxbits = 0u;
}

// ---------------- weight pre-packing (c_w2 only) ----------------
__global__ void pack_kernel(const float* __restrict__ c_w2) {
    int t0 = blockIdx.x * blockDim.x + threadIdx.x;
    int stride = gridDim.x * blockDim.x;
    for (int i = t0; i < 64 * 8; i += stride) {
        int kp = i >> 3, j = i & 7;
        g_CW2p[i] = packf2(c_w2[(2 * kp) * 8 + j], c_w2[(2 * kp + 1) * 8 + j]);
    }
}

// ---------------- per-node precompute: csum, pooled_col ----------------
__global__ void node_pre_kernel(const float* __restrict__ coords,
                                const float* __restrict__ cw) {
    int n = blockIdx.x * blockDim.x + threadIdx.x;
    if (n >= NN) return;
    float px = 0.f, py = 0.f, pz = 0.f;
    int cs = 0;
#pragma unroll
    for (int c = 0; c < 8; c++) {
        float w = cw[n * 8 + c];
        if (w != 0.f) {
            cs++;
            px += coords[n * 24 + c * 3 + 0];
            py += coords[n * 24 + c * 3 + 1];
            pz += coords[n * 24 + c * 3 + 2];
        }
    }
    float inv = 1.f / ((float)cs + 0.001f);
    g_pcol[n * 3 + 0] = px * inv;
    g_pcol[n * 3 + 1] = py * inv;
    g_pcol[n * 3 + 2] = pz * inv;
    g_csum[n] = cs;
}

// ---------------- global max of squared channel distances ----------------
__global__ void max_kernel(const float* __restrict__ coords,
                           const int* __restrict__ el) {
    int e = blockIdx.x * blockDim.x + threadIdx.x;
    float m = 0.f;
    if (e < EE) {
        int src = el[e * 3 + 0];
        int tgt = el[e * 3 + 1];
        float ct[24], cs[24];
#pragma unroll
        for (int i = 0; i < 24; i++) {
            ct[i] = coords[(long)tgt * 24 + i];
            cs[i] = coords[(long)src * 24 + i];
        }
#pragma unroll
        for (int c = 0; c < 8; c++) {
#pragma unroll
            for (int d = 0; d < 8; d++) {
                float dx = ct[c * 3 + 0] - cs[d * 3 + 0];
                float dy = ct[c * 3 + 1] - cs[d * 3 + 1];
                float dz = ct[c * 3 + 2] - cs[d * 3 + 2];
                float ns = dx * dx + dy * dy + dz * dz;
                m = fmaxf(m, ns);
            }
        }
    }
#pragma unroll
    for (int o = 16; o > 0; o >>= 1)
        m = fmaxf(m, __shfl_xor_sync(0xffffffffu, m, o));
    if ((threadIdx.x & 31) == 0)
        atomicMax(&g_maxbits, __float_as_uint(m));
}

// ---------------- per-node GEMM via wmma tf32 (64-row tiles) ----------------
__global__ __launch_bounds__(NTHR, 3)
void node_gemm_kernel(const float* __restrict__ h,
                      const float* __restrict__ m_w1) {
    __shared__ __align__(128) float hs[64 * MS];
    const int tid = threadIdx.x;
    const int base = blockIdx.x * 64;

    for (int idx = tid; idx < 64 * 128; idx += NTHR) {
        int n = idx >> 7, k = idx & 127;
        int gn = base + n;
        hs[n * MS + k] = (gn < NN) ? h[(long)gn * 128 + k] : 0.f;
    }
    __syncthreads();

    wmma_gemm_64x128x128(hs, m_w1,             &g_Ah[(long)base * 128], 128, tid);
    wmma_gemm_64x128x128(hs, m_w1 + 128 * 128, &g_Bh[(long)base * 128], 128, tid);
}

// ---------------- edge preprocessing: one edge per warp (R6 version) ----------------
__global__ __launch_bounds__(256)
void edge_pre_kernel(const float* __restrict__ coords,
                     const float* __restrict__ ca,
                     const float* __restrict__ cw,
                     const float* __restrict__ edge_weights,
                     const int* __restrict__ el,
                     const float* __restrict__ rl_w,
                     const float* __restrict__ rl_b,
                     const float* __restrict__ w_r) {
    __shared__ float wscr[8][320];
    const int wid = threadIdx.x >> 5;
    const int lane = threadIdx.x & 31;
    const long ge = (long)blockIdx.x * 8 + wid;
    if (ge >= (long)EE) return;

    float gmax = sqrtf(__uint_as_float(g_maxbits));
    float inv_g = 1.f / (gmax + 0.001f);

    float* WS  = &wscr[wid][0];
    float* At  = WS;
    float* Bs  = WS + 64;
    float* Mm  = WS + 128;
    float* Tt  = WS + 192;
    float* cwt = WS + 256;
    float* cws = WS + 264;
    float* ctb = WS + 272;
    float* csb = WS + 296;

    int src = el[ge * 3 + 0];
    int tgt = el[ge * 3 + 1];
    int rel = el[ge * 3 + 2];

    At[lane]      = ca[(long)tgt * 64 + lane];
    At[lane + 32] = ca[(long)tgt * 64 + lane + 32];
    Bs[lane]      = ca[(long)src * 64 + lane];
    Bs[lane + 32] = ca[(long)src * 64 + lane + 32];
    if (lane < 8) { cwt[lane] = cw[(long)tgt * 8 + lane]; cws[lane] = cw[(long)src * 8 + lane]; }
    if (lane < 24) { ctb[lane] = coords[(long)tgt * 24 + lane]; csb[lane] = coords[(long)src * 24 + lane]; }
    __syncwarp();

#pragma unroll
    for (int half = 0; half < 2; half++) {
        int idx = lane + half * 32;
        int c = idx >> 3, d = idx & 7;
        float dx = ctb[c * 3 + 0] - csb[d * 3 + 0];
        float dy = ctb[c * 3 + 1] - csb[d * 3 + 1];
        float dz = ctb[c * 3 + 2] - csb[d * 3 + 2];
        float ns = dx * dx + dy * dy + dz * dz;
        float nrm = (ns > 0.f) ? ns * rsqrtf(ns) : 0.f;
        Mm[idx] = nrm * inv_g * cwt[c] * cws[d];
    }
    __syncwarp();

#pragma unroll
    for (int half = 0; half < 2; half++) {
        int idx = lane + half * 32;
        int a = idx >> 3, d = idx & 7;
        float t = 0.f;
#pragma unroll
        for (int c = 0; c < 8; c++) t = fmaf(At[c * 8 + a], Mm[c * 8 + d], t);
        Tt[idx] = t;
    }
    __syncwarp();

    float r0 = 0.f, r1 = 0.f;
    {
        int a = lane >> 3, b = lane & 7;
#pragma unroll
        for (int d = 0; d < 8; d++) r0 = fmaf(Tt[a * 8 + d], Bs[d * 8 + b], r0);
        int idx = lane + 32;
        a = idx >> 3; b = idx & 7;
#pragma unroll
        for (int d = 0; d < 8; d++) r1 = fmaf(Tt[a * 8 + d], Bs[d * 8 + b], r1);
    }
    float ss = r0 * r0 + r1 * r1;
#pragma unroll
    for (int o = 16; o > 0; o >>= 1) ss += __shfl_xor_sync(0xffffffffu, ss, o);
    float invn = 1.f / (sqrtf(ss) + 0.001f);
    Mm[lane] = r0;
    Mm[lane + 32] = r1;
    __syncwarp();

    if (lane < 8) {
        float acc = 0.f;
#pragma unroll
        for (int k = 0; k < 64; k++) acc = fmaf(Mm[k], rl_w[k * 8 + lane], acc);
        g_rad[ge * 8 + lane] = acc * invn + rl_b[lane];
    }
    if (lane < 24) {
        int k = lane % 3;
        g_cdiff[ge * 24 + lane] = ctb[lane] - g_pcol[(long)src * 3 + k];
    }
    if (lane == 0) {
        int cs = g_csum[tgt];
        int ts = cs - 1;
        ts = ts < 0 ? 0 : (ts > 7 ? 7 : ts);
        g_meta[ge] = make_int4(tgt, src, ts, __float_as_int(edge_weights[ge]));
        g_wr[ge] = w_r[rel];
    }
}

// ---------------- fused edge GEMM kernel: wmma tf32, 64-edge tiles ----------------
struct __align__(128) EdgeSmem {
    float ms1[TILE_E * MS];    // m1 (silu'd) / later cf
    float ms2[TILE_E * MS];    // m
    float w1c[8 * 128];        // m_w1 rows 256..263 (radial part)
    float b1s[128];
    float b2s[128];
    float cb1s[128];
    float rad[TILE_E * 8];
    float ef[TILE_E * 8];
    int   s_tgt[TILE_E];
    int   s_src[TILE_E];
    float s_ew[TILE_E];
    float s_wr[TILE_E];
    int   s_ts[TILE_E];
};

// in-place bias + silu over TILE_E x 128 tile (stride MS)
__device__ __forceinline__ void bias_silu_pass(float* __restrict__ buf,
                                               const float* __restrict__ bias,
                                               int tid) {
    for (int idx = tid; idx < TILE_E * 32; idx += NTHR) {
        int e = idx >> 5, jq = idx & 31;
        int j = jq * 4;
        float4 v  = *(const float4*)&buf[e * MS + j];
        float4 bb = *(const float4*)&bias[j];
        v.x = silu_f(v.x + bb.x);
        v.y = silu_f(v.y + bb.y);
        v.z = silu_f(v.z + bb.z);
        v.w = silu_f(v.w + bb.w);
        *(float4*)&buf[e * MS + j] = v;
    }
}

__global__ __launch_bounds__(NTHR, 2)
void edge_kernel(const float* __restrict__ m_w1,
                 const float* __restrict__ m_b1,
                 const float* __restrict__ m_w2,
                 const float* __restrict__ m_b2,
                 const float* __restrict__ c_w1,
                 const float* __restrict__ c_b1) {
    extern __shared__ char smem_raw[];
    EdgeSmem& sm = *reinterpret_cast<EdgeSmem*>(smem_raw);

    const int tid = threadIdx.x;
    const long tileBase = (long)blockIdx.x * TILE_E;

    // stage W1c (radial rows) + biases
    for (int i = tid; i < 8 * 128; i += NTHR) sm.w1c[i] = m_w1[256 * 128 + i];
    if (tid < 128) {
        sm.b1s[tid]  = m_b1[tid];
        sm.b2s[tid]  = m_b2[tid];
        sm.cb1s[tid] = c_b1[tid];
    }

    // load meta + rad (coalesced; EE is an exact multiple of TILE_E)
    if (tid < TILE_E) {
        long ge = tileBase + tid;
        int4 m = g_meta[ge];
        sm.s_tgt[tid] = m.x;
        sm.s_src[tid] = m.y;
        sm.s_ts[tid]  = m.z;
        sm.s_ew[tid]  = __int_as_float(m.w);
        sm.s_wr[tid]  = g_wr[ge];
    }
    for (int idx = tid; idx < TILE_E * 8; idx += NTHR)
        sm.rad[idx] = g_rad[tileBase * 8 + idx];
    __syncthreads();

    // ---- m1 = silu(Ah[tgt] + Bh[src] + rad @ W1c + b1) -> ms1 ----
    {
        const int e = tid >> 2;          // 64 edges
        const int q = tid & 3;           // 4 col-quarters of 32
        const int j0 = q * 32;
        int t = sm.s_tgt[e];
        int s = sm.s_src[e];
        float r[8];
#pragma unroll
        for (int k = 0; k < 8; k++) r[k] = sm.rad[e * 8 + k];
#pragma unroll
        for (int v = 0; v < 8; v++) {
            int j = j0 + v * 4;
            float4 a  = *(const float4*)&g_Ah[(long)t * 128 + j];
            float4 b  = *(const float4*)&g_Bh[(long)s * 128 + j];
            float4 bb = *(const float4*)&sm.b1s[j];
            float4 acc;
            acc.x = a.x + b.x + bb.x;
            acc.y = a.y + b.y + bb.y;
            acc.z = a.z + b.z + bb.z;
            acc.w = a.w + b.w + bb.w;
#pragma unroll
            for (int k = 0; k < 8; k++) {
                float4 w = *(const float4*)&sm.w1c[k * 128 + j];
                acc.x = fmaf(r[k], w.x, acc.x);
                acc.y = fmaf(r[k], w.y, acc.y);
                acc.z = fmaf(r[k], w.z, acc.z);
                acc.w = fmaf(r[k], w.w, acc.w);
            }
            float4 o;
            o.x = silu_f(acc.x); o.y = silu_f(acc.y);
            o.z = silu_f(acc.z); o.w = silu_f(acc.w);
            *(float4*)&sm.ms1[e * MS + j] = o;
        }
    }
    __syncthreads();

    // ---- GEMM2 via wmma tf32: ms2_raw = ms1 @ m_w2 ----
    wmma_gemm_64x128x128(sm.ms1, m_w2, sm.ms2, MS, tid);
    __syncthreads();
    bias_silu_pass(sm.ms2, sm.b2s, tid);   // ms2 = m = silu(. + b2)
    __syncthreads();

    // ---- GEMM3 via wmma tf32: ms1_raw = ms2 @ c_w1 ----
    wmma_gemm_64x128x128(sm.ms2, c_w1, sm.ms1, MS, tid);
    __syncthreads();
    bias_silu_pass(sm.ms1, sm.cb1s, tid);  // ms1 = cf = silu(. + cb1)
    __syncthreads();

    // ---- edge_feat = cf @ c_w2  (64 edges x 8), packed-K FFMA2 ----
    for (int idx = tid; idx < TILE_E * 8; idx += NTHR) {
        int e = idx >> 3;
        int j = idx & 7;
        ull acc = 0ull;
#pragma unroll 8
        for (int kp = 0; kp < 64; kp++) {
            ull cf = *(const ull*)&sm.ms1[e * MS + kp * 2];
            FMA2(acc, cf, g_CW2p[kp * 8 + j], acc);
        }
        sm.ef[e * 8 + j] = lo_f(acc) + hi_f(acc);
    }
    __syncthreads();

    // ---- aggregation atomics ----
    for (int idx = tid; idx < TILE_E * 128; idx += NTHR) {
        int e = idx >> 7, j = idx & 127;
        int t = sm.s_tgt[e];
        atomicAdd(&g_node_agg[(long)t * 128 + j], sm.ms2[e * MS + j] * sm.s_ew[e]);
    }
    for (int idx = tid; idx < TILE_E * 8; idx += NTHR) {
        int e = idx >> 3, a = idx & 7;
        int t = sm.s_tgt[e];
        int ts = sm.s_ts[e];
        int w = 8 - ts;
        int hi = a + w; if (hi > 8) hi = 8;
        float s = 0.f;
        for (int b = a; b < hi; b++) s += sm.ef[e * 8 + b];
        float pe = (s / (float)w) * sm.s_wr[e];
        long ge = tileBase + e;
#pragma unroll
        for (int k = 0; k < 3; k++)
            atomicAdd(&g_coord_sum[(long)t * 24 + a * 3 + k],
                      g_cdiff[ge * 24 + a * 3 + k] * pe);
    }
    if (tid < TILE_E) {
        atomicAdd(&g_cnt[sm.s_tgt[tid]], 1.f);
    }
}

// ---------------- node epilogue: wmma het GEMM + BN + silu + residuals ----------------
__global__ __launch_bounds__(NTHR, 3)
void node_out_kernel(const float* __restrict__ h,
                     const float* __restrict__ coords,
                     const float* __restrict__ het_w,
                     const float* __restrict__ het_b,
                     const float* __restrict__ gamma,
                     const float* __restrict__ beta,
                     float* __restrict__ out) {
    __shared__ __align__(128) float ag[32 * MS];
    __shared__ __align__(128) float og[32 * MS];
    const int tid = threadIdx.x;
    const int base = blockIdx.x * 32;
    const float INVS = 0.9999950000374996f;  // 1/sqrt(1+1e-5)

    for (int idx = tid; idx < 32 * 128; idx += NTHR) {
        int n = idx >> 7, k = idx & 127;
        int gn = base + n;
        ag[n * MS + k] = (gn < NN) ? g_node_agg[(long)gn * 128 + k] : 0.f;
    }
    __syncthreads();

    wmma_gemm_32x128x128(ag, het_w, og, MS, tid);
    __syncthreads();

    for (int idx = tid; idx < 32 * 32; idx += NTHR) {
        int n = idx >> 5, jq = idx & 31;
        int j = jq * 4;
        int gn = base + n;
        if (gn < NN) {
            float4 v  = *(const float4*)&og[n * MS + j];
            float4 hb = *(const float4*)&het_b[j];
            float4 gm = *(const float4*)&gamma[j];
            float4 bt = *(const float4*)&beta[j];
            float4 hv = *(const float4*)&h[(long)gn * 128 + j];
            float4 o;
            o.x = silu_f((v.x + hb.x) * INVS * gm.x + bt.x) + hv.x;
            o.y = silu_f((v.y + hb.y) * INVS * gm.y + bt.y) + hv.y;
            o.z = silu_f((v.z + hb.z) * INVS * gm.z + bt.z) + hv.z;
            o.w = silu_f((v.w + hb.w) * INVS * gm.w + bt.w) + hv.w;
            *(float4*)&out[(long)gn * 128 + j] = o;
        }
    }

    for (int idx = tid; idx < 32 * 24; idx += NTHR) {
        int n = idx / 24, k = idx % 24;
        int gn = base + n;
        if (gn < NN) {
            float c = fmaxf(g_cnt[gn], 1.f);
            out[(long)NN * 128 + (long)gn * 24 + k] =
                coords[(long)gn * 24 + k] + g_coord_sum[(long)gn * 24 + k] / c;
        }
    }
}

// ---------------- launch ----------------
extern "C" void kernel_launch(void* const* d_in, const int* in_sizes, int n_in,
                              void* d_out, int out_size) {
    (void)in_sizes; (void)n_in; (void)out_size;
    const float* h      = (const float*)d_in[0];
    const float* coords = (const float*)d_in[1];
    const float* ca     = (const float*)d_in[2];
    const float* cw     = (const float*)d_in[3];
    const float* ew     = (const float*)d_in[4];
    const int*   el     = (const int*)d_in[5];
    const float* rl_w   = (const float*)d_in[6];
    const float* rl_b   = (const float*)d_in[7];
    const float* m_w1   = (const float*)d_in[8];
    const float* m_b1   = (const float*)d_in[9];
    const float* m_w2   = (const float*)d_in[10];
    const float* m_b2   = (const float*)d_in[11];
    const float* c_w1   = (const float*)d_in[12];
    const float* c_b1   = (const float*)d_in[13];
    const float* c_w2   = (const float*)d_in[14];
    const float* het_w  = (const float*)d_in[15];
    const float* het_b  = (const float*)d_in[16];
    const float* gamma  = (const float*)d_in[17];
    const float* beta   = (const float*)d_in[18];
    const float* w_r    = (const float*)d_in[19];
    float* out = (float*)d_out;

    cudaFuncSetAttribute(edge_kernel, cudaFuncAttributeMaxDynamicSharedMemorySize,
                         (int)sizeof(EdgeSmem));

    zero_kernel<<<2048, 256>>>();
    pack_kernel<<<8, 64>>>(c_w2);
    node_pre_kernel<<<(NN + 255) / 256, 256>>>(coords, cw);
    node_gemm_kernel<<<(NN + 63) / 64, NTHR>>>(h, m_w1);
    max_kernel<<<(EE + 255) / 256, 256>>>(coords, el);
    edge_pre_kernel<<<(EE + 7) / 8, 256>>>(coords, ca, cw, ew, el, rl_w, rl_b, w_r);
    edge_kernel<<<EE / TILE_E, NTHR, sizeof(EdgeSmem)>>>(
        m_w1, m_b1, m_w2, m_b2, c_w1, c_b1);
    node_out_kernel<<<(NN + 31) / 32, NTHR>>>(h, coords, het_w, het_b, gamma, beta, out);
}

// round 14
// speedup vs baseline: 1.0738x; 1.0738x over previous
#include <cuda_runtime.h>
#include <mma.h>
#include <math.h>

using namespace nvcuda;

#define NN 50000
#define EE 400000
#define DD 128
#define CC 8

#define TILE_E 32
#define NTHR 256
#define MS 132   // row stride in floats (132*4 = 528 B, 16B-aligned rows)

typedef unsigned long long ull;

// ---------------- device scratch (no allocations allowed) ----------------
__device__ float g_node_agg[NN * DD];
__device__ float g_coord_sum[NN * CC * 3];
__device__ float g_cnt[NN];
__device__ float g_pcol[NN * 3];
__device__ int   g_csum[NN];
__device__ unsigned int g_maxbits;
__device__ float g_Ah[(NN + 64) * DD];   // +64 rows padding for wmma tile overrun
__device__ float g_Bh[(NN + 64) * DD];

// edge-pre outputs
__device__ float g_rad[EE * 8];
__device__ float g_cdiff[EE * 24];
__device__ int4  g_meta[EE];
__device__ float g_wr[EE];

// packed weights for the small FFMA2 path
__device__ ull g_CW2p[64 * 8];     // c_w2

__device__ __forceinline__ float silu_f(float x) {
    return x * (1.0f / (1.0f + __expf(-x)));
}
__device__ __forceinline__ ull packf2(float lo, float hi) {
    return ((ull)__float_as_uint(hi) << 32) | (ull)__float_as_uint(lo);
}
__device__ __forceinline__ float lo_f(ull p) { return __uint_as_float((unsigned)(p & 0xffffffffull)); }
__device__ __forceinline__ float hi_f(ull p) { return __uint_as_float((unsigned)(p >> 32)); }

#define FMA2(d, a, b, c) asm("fma.rn.f32x2 %0, %1, %2, %3;" : "=l"(d) : "l"(a), "l"(b), "l"(c))

// ---------------- wmma helpers ----------------
// 64-row tile GEMM (node_gemm): dst = src(64x128, MS) @ W(128x128)
__device__ __forceinline__ void wmma_gemm_64x128x128(const float* __restrict__ src,
                                                     const float* __restrict__ W,
                                                     float* __restrict__ dst,
                                                     int dst_stride,
                                                     int tid) {
    const int w   = tid >> 5;
    const int mt  = w & 3;
    const int nt0 = (w >> 2) * 4;

    wmma::fragment<wmma::accumulator, 16, 16, 8, float> c[4];
#pragma unroll
    for (int j = 0; j < 4; j++) wmma::fill_fragment(c[j], 0.f);

    for (int k = 0; k < 16; k++) {
        wmma::fragment<wmma::matrix_a, 16, 16, 8, wmma::precision::tf32, wmma::row_major> fa;
        wmma::load_matrix_sync(fa, src + (mt * 16) * MS + k * 8, MS);
#pragma unroll
        for (int i = 0; i < fa.num_elements; i++) fa.x[i] = wmma::__float_to_tf32(fa.x[i]);
#pragma unroll
        for (int j = 0; j < 4; j++) {
            wmma::fragment<wmma::matrix_b, 16, 16, 8, wmma::precision::tf32, wmma::row_major> fb;
            wmma::load_matrix_sync(fb, W + (k * 8) * 128 + (nt0 + j) * 16, 128);
#pragma unroll
            for (int i = 0; i < fb.num_elements; i++) fb.x[i] = wmma::__float_to_tf32(fb.x[i]);
            wmma::mma_sync(c[j], fa, fb, c[j]);
        }
    }
#pragma unroll
    for (int j = 0; j < 4; j++)
        wmma::store_matrix_sync(dst + (mt * 16) * dst_stride + (nt0 + j) * 16, c[j],
                                dst_stride, wmma::mem_row_major);
}

// 32-row tile GEMM + fused warp-local bias+silu epilogue (edge kernel).
// Warp w: m-tile mt=w&1 (rows 16mt..16mt+16), n-tiles nt0,nt0+1 (cols 16nt0..16nt0+32).
// After storing its own region, the warp applies bias+silu to exactly that region
// (warp-private data: only __syncwarp needed before the block-level consumer sync).
template <bool BIAS_SILU>
__device__ __forceinline__ void wmma_gemm_32x128x128(const float* __restrict__ src,
                                                     const float* __restrict__ W,
                                                     float* __restrict__ dst,
                                                     int dst_stride,
                                                     const float* __restrict__ bias,
                                                     int tid) {
    const int w   = tid >> 5;
    const int mt  = w & 1;
    const int nt0 = (w >> 1) * 2;

    wmma::fragment<wmma::accumulator, 16, 16, 8, float> c0, c1;
    wmma::fill_fragment(c0, 0.f);
    wmma::fill_fragment(c1, 0.f);

    for (int k = 0; k < 16; k++) {
        wmma::fragment<wmma::matrix_a, 16, 16, 8, wmma::precision::tf32, wmma::row_major> fa;
        wmma::fragment<wmma::matrix_b, 16, 16, 8, wmma::precision::tf32, wmma::row_major> fb0, fb1;
        wmma::load_matrix_sync(fa, src + (mt * 16) * MS + k * 8, MS);
#pragma unroll
        for (int i = 0; i < fa.num_elements; i++) fa.x[i] = wmma::__float_to_tf32(fa.x[i]);
        wmma::load_matrix_sync(fb0, W + (k * 8) * 128 + nt0 * 16, 128);
        wmma::load_matrix_sync(fb1, W + (k * 8) * 128 + (nt0 + 1) * 16, 128);
#pragma unroll
        for (int i = 0; i < fb0.num_elements; i++) fb0.x[i] = wmma::__float_to_tf32(fb0.x[i]);
#pragma unroll
        for (int i = 0; i < fb1.num_elements; i++) fb1.x[i] = wmma::__float_to_tf32(fb1.x[i]);
        wmma::mma_sync(c0, fa, fb0, c0);
        wmma::mma_sync(c1, fa, fb1, c1);
    }
    wmma::store_matrix_sync(dst + (mt * 16) * dst_stride + nt0 * 16, c0, dst_stride, wmma::mem_row_major);
    wmma::store_matrix_sync(dst + (mt * 16) * dst_stride + (nt0 + 1) * 16, c1, dst_stride, wmma::mem_row_major);

    if (BIAS_SILU) {
        __syncwarp();
        const int lane = tid & 31;
        // warp region: rows [16mt, 16mt+16), cols [16nt0, 16nt0+32)
        // lane -> row 16mt + (lane&15), col half (lane>>4): 16 cols = 4 float4
        int row = mt * 16 + (lane & 15);
        int col0 = nt0 * 16 + (lane >> 4) * 16;
        float* p = dst + row * dst_stride;
#pragma unroll
        for (int v = 0; v < 4; v++) {
            int j = col0 + v * 4;
            float4 x  = *(const float4*)&p[j];
            float4 bb = *(const float4*)&bias[j];
            x.x = silu_f(x.x + bb.x);
            x.y = silu_f(x.y + bb.y);
            x.z = silu_f(x.z + bb.z);
            x.w = silu_f(x.w + bb.w);
            *(float4*)&p[j] = x;
        }
    }
}

// ---------------- zero scratch ----------------
__global__ void zero_kernel() {
    long t0 = (long)blockIdx.x * blockDim.x + threadIdx.x;
    long stride = (long)gridDim.x * blockDim.x;
    for (long i = t0; i < (long)NN * DD; i += stride) g_node_agg[i] = 0.f;
    for (long i = t0; i < (long)NN * 24; i += stride) g_coord_sum[i] = 0.f;
    for (long i = t0; i < NN; i += stride) g_cnt[i] = 0.f;
    if (t0 == 0) g_maxbits = 0u;
}

// ---------------- weight pre-packing (c_w2 only) ----------------
__global__ void pack_kernel(const float* __restrict__ c_w2) {
    int t0 = blockIdx.x * blockDim.x + threadIdx.x;
    int stride = gridDim.x * blockDim.x;
    for (int i = t0; i < 64 * 8; i += stride) {
        int kp = i >> 3, j = i & 7;
        g_CW2p[i] = packf2(c_w2[(2 * kp) * 8 + j], c_w2[(2 * kp + 1) * 8 + j]);
    }
}

// ---------------- per-node precompute: csum, pooled_col ----------------
__global__ void node_pre_kernel(const float* __restrict__ coords,
                                const float* __restrict__ cw) {
    int n = blockIdx.x * blockDim.x + threadIdx.x;
    if (n >= NN) return;
    float px = 0.f, py = 0.f, pz = 0.f;
    int cs = 0;
#pragma unroll
    for (int c = 0; c < 8; c++) {
        float w = cw[n * 8 + c];
        if (w != 0.f) {
            cs++;
            px += coords[n * 24 + c * 3 + 0];
            py += coords[n * 24 + c * 3 + 1];
            pz += coords[n * 24 + c * 3 + 2];
        }
    }
    float inv = 1.f / ((float)cs + 0.001f);
    g_pcol[n * 3 + 0] = px * inv;
    g_pcol[n * 3 + 1] = py * inv;
    g_pcol[n * 3 + 2] = pz * inv;
    g_csum[n] = cs;
}

// ---------------- global max of squared channel distances ----------------
__global__ void max_kernel(const float* __restrict__ coords,
                           const int* __restrict__ el) {
    int e = blockIdx.x * blockDim.x + threadIdx.x;
    float m = 0.f;
    if (e < EE) {
        int src = el[e * 3 + 0];
        int tgt = el[e * 3 + 1];
        float ct[24], cs[24];
#pragma unroll
        for (int i = 0; i < 24; i++) {
            ct[i] = coords[(long)tgt * 24 + i];
            cs[i] = coords[(long)src * 24 + i];
        }
#pragma unroll
        for (int c = 0; c < 8; c++) {
#pragma unroll
            for (int d = 0; d < 8; d++) {
                float dx = ct[c * 3 + 0] - cs[d * 3 + 0];
                float dy = ct[c * 3 + 1] - cs[d * 3 + 1];
                float dz = ct[c * 3 + 2] - cs[d * 3 + 2];
                float ns = dx * dx + dy * dy + dz * dz;
                m = fmaxf(m, ns);
            }
        }
    }
#pragma unroll
    for (int o = 16; o > 0; o >>= 1)
        m = fmaxf(m, __shfl_xor_sync(0xffffffffu, m, o));
    if ((threadIdx.x & 31) == 0)
        atomicMax(&g_maxbits, __float_as_uint(m));
}

// ---------------- per-node GEMM via wmma tf32 (64-row tiles, R13 keeper) ----------------
__global__ __launch_bounds__(NTHR, 3)
void node_gemm_kernel(const float* __restrict__ h,
                      const float* __restrict__ m_w1) {
    __shared__ __align__(128) float hs[64 * MS];
    const int tid = threadIdx.x;
    const int base = blockIdx.x * 64;

    for (int idx = tid; idx < 64 * 128; idx += NTHR) {
        int n = idx >> 7, k = idx & 127;
        int gn = base + n;
        hs[n * MS + k] = (gn < NN) ? h[(long)gn * 128 + k] : 0.f;
    }
    __syncthreads();

    wmma_gemm_64x128x128(hs, m_w1,             &g_Ah[(long)base * 128], 128, tid);
    wmma_gemm_64x128x128(hs, m_w1 + 128 * 128, &g_Bh[(long)base * 128], 128, tid);
}

// ---------------- edge preprocessing: one edge per warp (R6 version) ----------------
__global__ __launch_bounds__(256)
void edge_pre_kernel(const float* __restrict__ coords,
                     const float* __restrict__ ca,
                     const float* __restrict__ cw,
                     const float* __restrict__ edge_weights,
                     const int* __restrict__ el,
                     const float* __restrict__ rl_w,
                     const float* __restrict__ rl_b,
                     const float* __restrict__ w_r) {
    __shared__ float wscr[8][320];
    const int wid = threadIdx.x >> 5;
    const int lane = threadIdx.x & 31;
    const long ge = (long)blockIdx.x * 8 + wid;
    if (ge >= (long)EE) return;

    float gmax = sqrtf(__uint_as_float(g_maxbits));
    float inv_g = 1.f / (gmax + 0.001f);

    float* WS  = &wscr[wid][0];
    float* At  = WS;
    float* Bs  = WS + 64;
    float* Mm  = WS + 128;
    float* Tt  = WS + 192;
    float* cwt = WS + 256;
    float* cws = WS + 264;
    float* ctb = WS + 272;
    float* csb = WS + 296;

    int src = el[ge * 3 + 0];
    int tgt = el[ge * 3 + 1];
    int rel = el[ge * 3 + 2];

    At[lane]      = ca[(long)tgt * 64 + lane];
    At[lane + 32] = ca[(long)tgt * 64 + lane + 32];
    Bs[lane]      = ca[(long)src * 64 + lane];
    Bs[lane + 32] = ca[(long)src * 64 + lane + 32];
    if (lane < 8) { cwt[lane] = cw[(long)tgt * 8 + lane]; cws[lane] = cw[(long)src * 8 + lane]; }
    if (lane < 24) { ctb[lane] = coords[(long)tgt * 24 + lane]; csb[lane] = coords[(long)src * 24 + lane]; }
    __syncwarp();

#pragma unroll
    for (int half = 0; half < 2; half++) {
        int idx = lane + half * 32;
        int c = idx >> 3, d = idx & 7;
        float dx = ctb[c * 3 + 0] - csb[d * 3 + 0];
        float dy = ctb[c * 3 + 1] - csb[d * 3 + 1];
        float dz = ctb[c * 3 + 2] - csb[d * 3 + 2];
        float ns = dx * dx + dy * dy + dz * dz;
        float nrm = (ns > 0.f) ? ns * rsqrtf(ns) : 0.f;
        Mm[idx] = nrm * inv_g * cwt[c] * cws[d];
    }
    __syncwarp();

#pragma unroll
    for (int half = 0; half < 2; half++) {
        int idx = lane + half * 32;
        int a = idx >> 3, d = idx & 7;
        float t = 0.f;
#pragma unroll
        for (int c = 0; c < 8; c++) t = fmaf(At[c * 8 + a], Mm[c * 8 + d], t);
        Tt[idx] = t;
    }
    __syncwarp();

    float r0 = 0.f, r1 = 0.f;
    {
        int a = lane >> 3, b = lane & 7;
#pragma unroll
        for (int d = 0; d < 8; d++) r0 = fmaf(Tt[a * 8 + d], Bs[d * 8 + b], r0);
        int idx = lane + 32;
        a = idx >> 3; b = idx & 7;
#pragma unroll
        for (int d = 0; d < 8; d++) r1 = fmaf(Tt[a * 8 + d], Bs[d * 8 + b], r1);
    }
    float ss = r0 * r0 + r1 * r1;
#pragma unroll
    for (int o = 16; o > 0; o >>= 1) ss += __shfl_xor_sync(0xffffffffu, ss, o);
    float invn = 1.f / (sqrtf(ss) + 0.001f);
    Mm[lane] = r0;
    Mm[lane + 32] = r1;
    __syncwarp();

    if (lane < 8) {
        float acc = 0.f;
#pragma unroll
        for (int k = 0; k < 64; k++) acc = fmaf(Mm[k], rl_w[k * 8 + lane], acc);
        g_rad[ge * 8 + lane] = acc * invn + rl_b[lane];
    }
    if (lane < 24) {
        int k = lane % 3;
        g_cdiff[ge * 24 + lane] = ctb[lane] - g_pcol[(long)src * 3 + k];
    }
    if (lane == 0) {
        int cs = g_csum[tgt];
        int ts = cs - 1;
        ts = ts < 0 ? 0 : (ts > 7 ? 7 : ts);
        g_meta[ge] = make_int4(tgt, src, ts, __float_as_int(edge_weights[ge]));
        g_wr[ge] = w_r[rel];
    }
}

// ---------------- fused edge GEMM kernel (R12 geometry + fused epilogues) ----------------
struct __align__(128) EdgeSmem {
    float ms1[TILE_E * MS];    // m1 (silu'd) / later cf
    float ms2[TILE_E * MS];    // m
    float w1c[8 * 128];        // m_w1 rows 256..263 (radial part)
    float b1s[128];
    float b2s[128];
    float cb1s[128];
    float rad[TILE_E * 8];
    float ef[TILE_E * 8];
    int   s_tgt[TILE_E];
    int   s_src[TILE_E];
    float s_ew[TILE_E];
    float s_wr[TILE_E];
    int   s_ts[TILE_E];
};

__global__ __launch_bounds__(NTHR, 3)
void edge_kernel(const float* __restrict__ m_w1,
                 const float* __restrict__ m_b1,
                 const float* __restrict__ m_w2,
                 const float* __restrict__ m_b2,
                 const float* __restrict__ c_w1,
                 const float* __restrict__ c_b1) {
    extern __shared__ char smem_raw[];
    EdgeSmem& sm = *reinterpret_cast<EdgeSmem*>(smem_raw);

    const int tid = threadIdx.x;
    const long tileBase = (long)blockIdx.x * TILE_E;

    // stage W1c (radial rows) + biases
    for (int i = tid; i < 8 * 128; i += NTHR) sm.w1c[i] = m_w1[256 * 128 + i];
    if (tid < 128) {
        sm.b1s[tid]  = m_b1[tid];
        sm.b2s[tid]  = m_b2[tid];
        sm.cb1s[tid] = c_b1[tid];
    }

    // load meta + rad (coalesced)
    if (tid < TILE_E) {
        long ge = tileBase + tid;
        int4 m = g_meta[ge];
        sm.s_tgt[tid] = m.x;
        sm.s_src[tid] = m.y;
        sm.s_ts[tid]  = m.z;
        sm.s_ew[tid]  = __int_as_float(m.w);
        sm.s_wr[tid]  = g_wr[ge];
    }
    if (tid < TILE_E * 8)
        sm.rad[tid] = g_rad[tileBase * 8 + tid];
    __syncthreads();

    // ---- m1 = silu(Ah[tgt] + Bh[src] + rad @ W1c + b1) -> ms1 ----
    {
        const int e = tid >> 3;          // 32 edges
        const int q = tid & 7;           // 8 col-quarters of 16
        const int j0 = q * 16;
        int t = sm.s_tgt[e];
        int s = sm.s_src[e];
        float r[8];
#pragma unroll
        for (int k = 0; k < 8; k++) r[k] = sm.rad[e * 8 + k];
#pragma unroll
        for (int v = 0; v < 4; v++) {
            int j = j0 + v * 4;
            float4 a  = *(const float4*)&g_Ah[(long)t * 128 + j];
            float4 b  = *(const float4*)&g_Bh[(long)s * 128 + j];
            float4 bb = *(const float4*)&sm.b1s[j];
            float4 acc;
            acc.x = a.x + b.x + bb.x;
            acc.y = a.y + b.y + bb.y;
            acc.z = a.z + b.z + bb.z;
            acc.w = a.w + b.w + bb.w;
#pragma unroll
            for (int k = 0; k < 8; k++) {
                float4 w = *(const float4*)&sm.w1c[k * 128 + j];
                acc.x = fmaf(r[k], w.x, acc.x);
                acc.y = fmaf(r[k], w.y, acc.y);
                acc.z = fmaf(r[k], w.z, acc.z);
                acc.w = fmaf(r[k], w.w, acc.w);
            }
            float4 o;
            o.x = silu_f(acc.x); o.y = silu_f(acc.y);
            o.z = silu_f(acc.z); o.w = silu_f(acc.w);
            *(float4*)&sm.ms1[e * MS + j] = o;
        }
    }
    __syncthreads();

    // ---- GEMM2 (wmma tf32, fused bias+silu): ms2 = silu(ms1@m_w2 + b2) ----
    wmma_gemm_32x128x128<true>(sm.ms1, m_w2, sm.ms2, MS, sm.b2s, tid);
    __syncthreads();

    // ---- GEMM3 (wmma tf32, fused bias+silu): ms1 = silu(ms2@c_w1 + cb1) ----
    wmma_gemm_32x128x128<true>(sm.ms2, c_w1, sm.ms1, MS, sm.cb1s, tid);
    __syncthreads();

    // ---- edge_feat = cf @ c_w2  (32 edges x 8), packed-K FFMA2 ----
    {
        int e = tid >> 3;
        int j = tid & 7;
        ull acc = 0ull;
#pragma unroll 8
        for (int kp = 0; kp < 64; kp++) {
            ull cf = *(const ull*)&sm.ms1[e * MS + kp * 2];
            FMA2(acc, cf, g_CW2p[kp * 8 + j], acc);
        }
        sm.ef[e * 8 + j] = lo_f(acc) + hi_f(acc);
    }
    __syncthreads();

    // ---- aggregation atomics ----
    for (int idx = tid; idx < TILE_E * 128; idx += NTHR) {
        int e = idx >> 7, j = idx & 127;
        int t = sm.s_tgt[e];
        atomicAdd(&g_node_agg[(long)t * 128 + j], sm.ms2[e * MS + j] * sm.s_ew[e]);
    }
    if (tid < TILE_E * 8) {
        int e = tid >> 3, a = tid & 7;
        int t = sm.s_tgt[e];
        int ts = sm.s_ts[e];
        int w = 8 - ts;
        int hi = a + w; if (hi > 8) hi = 8;
        float s = 0.f;
        for (int b = a; b < hi; b++) s += sm.ef[e * 8 + b];
        float pe = (s / (float)w) * sm.s_wr[e];
        long ge = tileBase + e;
#pragma unroll
        for (int k = 0; k < 3; k++)
            atomicAdd(&g_coord_sum[(long)t * 24 + a * 3 + k],
                      g_cdiff[ge * 24 + a * 3 + k] * pe);
    }
    if (tid < TILE_E) {
        atomicAdd(&g_cnt[sm.s_tgt[tid]], 1.f);
    }
}

// ---------------- node epilogue: wmma het GEMM + BN + silu + residuals ----------------
__global__ __launch_bounds__(NTHR, 3)
void node_out_kernel(const float* __restrict__ h,
                     const float* __restrict__ coords,
                     const float* __restrict__ het_w,
                     const float* __restrict__ het_b,
                     const float* __restrict__ gamma,
                     const float* __restrict__ beta,
                     float* __restrict__ out) {
    __shared__ __align__(128) float ag[32 * MS];
    __shared__ __align__(128) float og[32 * MS];
    const int tid = threadIdx.x;
    const int base = blockIdx.x * 32;
    const float INVS = 0.9999950000374996f;  // 1/sqrt(1+1e-5)

    for (int idx = tid; idx < 32 * 128; idx += NTHR) {
        int n = idx >> 7, k = idx & 127;
        int gn = base + n;
        ag[n * MS + k] = (gn < NN) ? g_node_agg[(long)gn * 128 + k] : 0.f;
    }
    __syncthreads();

    wmma_gemm_32x128x128<false>(ag, het_w, og, MS, nullptr, tid);
    __syncthreads();

    for (int idx = tid; idx < 32 * 32; idx += NTHR) {
        int n = idx >> 5, jq = idx & 31;
        int j = jq * 4;
        int gn = base + n;
        if (gn < NN) {
            float4 v  = *(const float4*)&og[n * MS + j];
            float4 hb = *(const float4*)&het_b[j];
            float4 gm = *(const float4*)&gamma[j];
            float4 bt = *(const float4*)&beta[j];
            float4 hv = *(const float4*)&h[(long)gn * 128 + j];
            float4 o;
            o.x = silu_f((v.x + hb.x) * INVS * gm.x + bt.x) + hv.x;
            o.y = silu_f((v.y + hb.y) * INVS * gm.y + bt.y) + hv.y;
            o.z = silu_f((v.z + hb.z) * INVS * gm.z + bt.z) + hv.z;
            o.w = silu_f((v.w + hb.w) * INVS * gm.w + bt.w) + hv.w;
            *(float4*)&out[(long)gn * 128 + j] = o;
        }
    }

    for (int idx = tid; idx < 32 * 24; idx += NTHR) {
        int n = idx / 24, k = idx % 24;
        int gn = base + n;
        if (gn < NN) {
            float c = fmaxf(g_cnt[gn], 1.f);
            out[(long)NN * 128 + (long)gn * 24 + k] =
                coords[(long)gn * 24 + k] + g_coord_sum[(long)gn * 24 + k] / c;
        }
    }
}

// ---------------- launch ----------------
extern "C" void kernel_launch(void* const* d_in, const int* in_sizes, int n_in,
                              void* d_out, int out_size) {
    (void)in_sizes; (void)n_in; (void)out_size;
    const float* h      = (const float*)d_in[0];
    const float* coords = (const float*)d_in[1];
    const float* ca     = (const float*)d_in[2];
    const float* cw     = (const float*)d_in[3];
    const float* ew     = (const float*)d_in[4];
    const int*   el     = (const int*)d_in[5];
    const float* rl_w   = (const float*)d_in[6];
    const float* rl_b   = (const float*)d_in[7];
    const float* m_w1   = (const float*)d_in[8];
    const float* m_b1   = (const float*)d_in[9];
    const float* m_w2   = (const float*)d_in[10];
    const float* m_b2   = (const float*)d_in[11];
    const float* c_w1   = (const float*)d_in[12];
    const float* c_b1   = (const float*)d_in[13];
    const float* c_w2   = (const float*)d_in[14];
    const float* het_w  = (const float*)d_in[15];
    const float* het_b  = (const float*)d_in[16];
    const float* gamma  = (const float*)d_in[17];
    const float* beta   = (const float*)d_in[18];
    const float* w_r    = (const float*)d_in[19];
    float* out = (float*)d_out;

    cudaFuncSetAttribute(edge_kernel, cudaFuncAttributeMaxDynamicSharedMemorySize,
                         (int)sizeof(EdgeSmem));

    zero_kernel<<<2048, 256>>>();
    pack_kernel<<<8, 64>>>(c_w2);
    node_pre_kernel<<<(NN + 255) / 256, 256>>>(coords, cw);
    node_gemm_kernel<<<(NN + 63) / 64, NTHR>>>(h, m_w1);
    max_kernel<<<(EE + 255) / 256, 256>>>(coords, el);
    edge_pre_kernel<<<(EE + 7) / 8, 256>>>(coords, ca, cw, ew, el, rl_w, rl_b, w_r);
    edge_kernel<<<EE / TILE_E, NTHR, sizeof(EdgeSmem)>>>(
        m_w1, m_b1, m_w2, m_b2, c_w1, c_b1);
    node_out_kernel<<<(NN + 31) / 32, NTHR>>>(h, coords, het_w, het_b, gamma, beta, out);
}

// round 15
// speedup vs baseline: 1.1017x; 1.0260x over previous
#include <cuda_runtime.h>
#include <cuda_bf16.h>
#include <mma.h>
#include <math.h>

using namespace nvcuda;

#define NN 50000
#define EE 400000
#define DD 128
#define CC 8

#define TILE_E 32
#define NTHR 256
#define MS 132    // fp32 row stride (16B-aligned rows)
#define MSB 136   // bf16 row stride (272 B = multiple of 16 B)

typedef unsigned long long ull;
typedef __nv_bfloat16 bf16;

// ---------------- device scratch (no allocations allowed) ----------------
__device__ float g_node_agg[NN * DD];
__device__ float g_coord_sum[NN * CC * 3];
__device__ float g_cnt[NN];
__device__ float g_pcol[NN * 3];
__device__ int   g_csum[NN];
__device__ unsigned int g_maxbits;
__device__ float g_Ah[(NN + 64) * DD];   // +64 rows padding for wmma tile overrun
__device__ float g_Bh[(NN + 64) * DD];

// edge-pre outputs
__device__ float g_rad[EE * 8];
__device__ float g_cdiff[EE * 24];
__device__ int4  g_meta[EE];
__device__ float g_wr[EE];

// bf16 weight copies for MMA
__device__ bf16 g_W1b[256 * 128];   // m_w1 rows 0..255 (W1a | W1b)
__device__ bf16 g_W2b[128 * 128];   // m_w2
__device__ bf16 g_CW1b[128 * 128];  // c_w1
__device__ bf16 g_HWb[128 * 128];   // het_w

// packed fp32 weights for the small FFMA2 path
__device__ ull g_CW2p[64 * 8];      // c_w2

__device__ __forceinline__ float silu_f(float x) {
    return x * (1.0f / (1.0f + __expf(-x)));
}
__device__ __forceinline__ ull packf2(float lo, float hi) {
    return ((ull)__float_as_uint(hi) << 32) | (ull)__float_as_uint(lo);
}
__device__ __forceinline__ float lo_f(ull p) { return __uint_as_float((unsigned)(p & 0xffffffffull)); }
__device__ __forceinline__ float hi_f(ull p) { return __uint_as_float((unsigned)(p >> 32)); }

__device__ __forceinline__ ull pack_bf16x4(float a, float b, float c, float d) {
    unsigned short h0 = __bfloat16_as_ushort(__float2bfloat16_rn(a));
    unsigned short h1 = __bfloat16_as_ushort(__float2bfloat16_rn(b));
    unsigned short h2 = __bfloat16_as_ushort(__float2bfloat16_rn(c));
    unsigned short h3 = __bfloat16_as_ushort(__float2bfloat16_rn(d));
    return ((ull)h3 << 48) | ((ull)h2 << 32) | ((ull)h1 << 16) | (ull)h0;
}

#define FMA2(d, a, b, c) asm("fma.rn.f32x2 %0, %1, %2, %3;" : "=l"(d) : "l"(a), "l"(b), "l"(c))

// ---------------- bf16 wmma helpers ----------------
// 32-row: dst(32x128 fp32, ds) = src(32x128 bf16, ss) @ W(128x128 bf16, ld 128)
// EPI: 0 = raw store; 1 = fused warp-local bias+silu (fp32); 2 = bias+silu fp32 + bf16 copy
template <int EPI>
__device__ __forceinline__ void wmma_bf16_32(const bf16* __restrict__ src, int ss,
                                             const bf16* __restrict__ W,
                                             float* __restrict__ dst, int ds,
                                             bf16* __restrict__ dstb, int dsb,
                                             const float* __restrict__ bias,
                                             int tid) {
    const int w   = tid >> 5;
    const int mt  = w & 1;
    const int nt0 = (w >> 1) * 2;

    wmma::fragment<wmma::accumulator, 16, 16, 16, float> c0, c1;
    wmma::fill_fragment(c0, 0.f);
    wmma::fill_fragment(c1, 0.f);

#pragma unroll
    for (int k = 0; k < 8; k++) {
        wmma::fragment<wmma::matrix_a, 16, 16, 16, bf16, wmma::row_major> fa;
        wmma::fragment<wmma::matrix_b, 16, 16, 16, bf16, wmma::row_major> fb0, fb1;
        wmma::load_matrix_sync(fa, src + (mt * 16) * ss + k * 16, ss);
        wmma::load_matrix_sync(fb0, W + (k * 16) * 128 + nt0 * 16, 128);
        wmma::load_matrix_sync(fb1, W + (k * 16) * 128 + (nt0 + 1) * 16, 128);
        wmma::mma_sync(c0, fa, fb0, c0);
        wmma::mma_sync(c1, fa, fb1, c1);
    }
    wmma::store_matrix_sync(dst + (mt * 16) * ds + nt0 * 16, c0, ds, wmma::mem_row_major);
    wmma::store_matrix_sync(dst + (mt * 16) * ds + (nt0 + 1) * 16, c1, ds, wmma::mem_row_major);

    if (EPI >= 1) {
        __syncwarp();
        const int lane = tid & 31;
        int row = mt * 16 + (lane & 15);
        int col0 = nt0 * 16 + (lane >> 4) * 16;
        float* p = dst + row * ds;
#pragma unroll
        for (int v = 0; v < 4; v++) {
            int j = col0 + v * 4;
            float4 x  = *(const float4*)&p[j];
            float4 bb = *(const float4*)&bias[j];
            x.x = silu_f(x.x + bb.x);
            x.y = silu_f(x.y + bb.y);
            x.z = silu_f(x.z + bb.z);
            x.w = silu_f(x.w + bb.w);
            *(float4*)&p[j] = x;
            if (EPI == 2)
                *(ull*)&dstb[row * dsb + j] = pack_bf16x4(x.x, x.y, x.z, x.w);
        }
    }
}

// 64-row: dst(64x128 fp32, ds) = src(64x128 bf16, ss) @ W(128x128 bf16)
__device__ __forceinline__ void wmma_bf16_64(const bf16* __restrict__ src, int ss,
                                             const bf16* __restrict__ W,
                                             float* __restrict__ dst, int ds,
                                             int tid) {
    const int w   = tid >> 5;
    const int mt  = w & 3;
    const int nt0 = (w >> 2) * 4;

    wmma::fragment<wmma::accumulator, 16, 16, 16, float> c[4];
#pragma unroll
    for (int j = 0; j < 4; j++) wmma::fill_fragment(c[j], 0.f);

#pragma unroll
    for (int k = 0; k < 8; k++) {
        wmma::fragment<wmma::matrix_a, 16, 16, 16, bf16, wmma::row_major> fa;
        wmma::load_matrix_sync(fa, src + (mt * 16) * ss + k * 16, ss);
#pragma unroll
        for (int j = 0; j < 4; j++) {
            wmma::fragment<wmma::matrix_b, 16, 16, 16, bf16, wmma::row_major> fb;
            wmma::load_matrix_sync(fb, W + (k * 16) * 128 + (nt0 + j) * 16, 128);
            wmma::mma_sync(c[j], fa, fb, c[j]);
        }
    }
#pragma unroll
    for (int j = 0; j < 4; j++)
        wmma::store_matrix_sync(dst + (mt * 16) * ds + (nt0 + j) * 16, c[j], ds, wmma::mem_row_major);
}

// ---------------- zero scratch ----------------
__global__ void zero_kernel() {
    long t0 = (long)blockIdx.x * blockDim.x + threadIdx.x;
    long stride = (long)gridDim.x * blockDim.x;
    for (long i = t0; i < (long)NN * DD; i += stride) g_node_agg[i] = 0.f;
    for (long i = t0; i < (long)NN * 24; i += stride) g_coord_sum[i] = 0.f;
    for (long i = t0; i < NN; i += stride) g_cnt[i] = 0.f;
    if (t0 == 0) g_maxbits = 0u;
}

// ---------------- weight pre-packing / bf16 conversion ----------------
__global__ void pack_kernel(const float* __restrict__ m_w1,
                            const float* __restrict__ m_w2,
                            const float* __restrict__ c_w1,
                            const float* __restrict__ c_w2,
                            const float* __restrict__ het_w) {
    int t0 = blockIdx.x * blockDim.x + threadIdx.x;
    int stride = gridDim.x * blockDim.x;
    for (int i = t0; i < 256 * 128; i += stride)
        g_W1b[i] = __float2bfloat16_rn(m_w1[i]);
    for (int i = t0; i < 128 * 128; i += stride) {
        g_W2b[i]  = __float2bfloat16_rn(m_w2[i]);
        g_CW1b[i] = __float2bfloat16_rn(c_w1[i]);
        g_HWb[i]  = __float2bfloat16_rn(het_w[i]);
    }
    for (int i = t0; i < 64 * 8; i += stride) {
        int kp = i >> 3, j = i & 7;
        g_CW2p[i] = packf2(c_w2[(2 * kp) * 8 + j], c_w2[(2 * kp + 1) * 8 + j]);
    }
}

// ---------------- per-node precompute: csum, pooled_col ----------------
__global__ void node_pre_kernel(const float* __restrict__ coords,
                                const float* __restrict__ cw) {
    int n = blockIdx.x * blockDim.x + threadIdx.x;
    if (n >= NN) return;
    float px = 0.f, py = 0.f, pz = 0.f;
    int cs = 0;
#pragma unroll
    for (int c = 0; c < 8; c++) {
        float w = cw[n * 8 + c];
        if (w != 0.f) {
            cs++;
            px += coords[n * 24 + c * 3 + 0];
            py += coords[n * 24 + c * 3 + 1];
            pz += coords[n * 24 + c * 3 + 2];
        }
    }
    float inv = 1.f / ((float)cs + 0.001f);
    g_pcol[n * 3 + 0] = px * inv;
    g_pcol[n * 3 + 1] = py * inv;
    g_pcol[n * 3 + 2] = pz * inv;
    g_csum[n] = cs;
}

// ---------------- global max of squared channel distances ----------------
__global__ void max_kernel(const float* __restrict__ coords,
                           const int* __restrict__ el) {
    int e = blockIdx.x * blockDim.x + threadIdx.x;
    float m = 0.f;
    if (e < EE) {
        int src = el[e * 3 + 0];
        int tgt = el[e * 3 + 1];
        float ct[24], cs[24];
#pragma unroll
        for (int i = 0; i < 24; i++) {
            ct[i] = coords[(long)tgt * 24 + i];
            cs[i] = coords[(long)src * 24 + i];
        }
#pragma unroll
        for (int c = 0; c < 8; c++) {
#pragma unroll
            for (int d = 0; d < 8; d++) {
                float dx = ct[c * 3 + 0] - cs[d * 3 + 0];
                float dy = ct[c * 3 + 1] - cs[d * 3 + 1];
                float dz = ct[c * 3 + 2] - cs[d * 3 + 2];
                float ns = dx * dx + dy * dy + dz * dz;
                m = fmaxf(m, ns);
            }
        }
    }
#pragma unroll
    for (int o = 16; o > 0; o >>= 1)
        m = fmaxf(m, __shfl_xor_sync(0xffffffffu, m, o));
    if ((threadIdx.x & 31) == 0)
        atomicMax(&g_maxbits, __float_as_uint(m));
}

// ---------------- per-node GEMM via bf16 wmma (64-row tiles) ----------------
__global__ __launch_bounds__(NTHR, 3)
void node_gemm_kernel(const float* __restrict__ h) {
    __shared__ __align__(128) bf16 hs[64 * MSB];
    const int tid = threadIdx.x;
    const int base = blockIdx.x * 64;

    for (int idx = tid; idx < 64 * 128; idx += NTHR) {
        int n = idx >> 7, k = idx & 127;
        int gn = base + n;
        hs[n * MSB + k] = __float2bfloat16_rn((gn < NN) ? h[(long)gn * 128 + k] : 0.f);
    }
    __syncthreads();

    wmma_bf16_64(hs, MSB, g_W1b,             &g_Ah[(long)base * 128], 128, tid);
    wmma_bf16_64(hs, MSB, g_W1b + 128 * 128, &g_Bh[(long)base * 128], 128, tid);
}

// ---------------- edge preprocessing: one edge per warp (R6 version) ----------------
__global__ __launch_bounds__(256)
void edge_pre_kernel(const float* __restrict__ coords,
                     const float* __restrict__ ca,
                     const float* __restrict__ cw,
                     const float* __restrict__ edge_weights,
                     const int* __restrict__ el,
                     const float* __restrict__ rl_w,
                     const float* __restrict__ rl_b,
                     const float* __restrict__ w_r) {
    __shared__ float wscr[8][320];
    const int wid = threadIdx.x >> 5;
    const int lane = threadIdx.x & 31;
    const long ge = (long)blockIdx.x * 8 + wid;
    if (ge >= (long)EE) return;

    float gmax = sqrtf(__uint_as_float(g_maxbits));
    float inv_g = 1.f / (gmax + 0.001f);

    float* WS  = &wscr[wid][0];
    float* At  = WS;
    float* Bs  = WS + 64;
    float* Mm  = WS + 128;
    float* Tt  = WS + 192;
    float* cwt = WS + 256;
    float* cws = WS + 264;
    float* ctb = WS + 272;
    float* csb = WS + 296;

    int src = el[ge * 3 + 0];
    int tgt = el[ge * 3 + 1];
    int rel = el[ge * 3 + 2];

    At[lane]      = ca[(long)tgt * 64 + lane];
    At[lane + 32] = ca[(long)tgt * 64 + lane + 32];
    Bs[lane]      = ca[(long)src * 64 + lane];
    Bs[lane + 32] = ca[(long)src * 64 + lane + 32];
    if (lane < 8) { cwt[lane] = cw[(long)tgt * 8 + lane]; cws[lane] = cw[(long)src * 8 + lane]; }
    if (lane < 24) { ctb[lane] = coords[(long)tgt * 24 + lane]; csb[lane] = coords[(long)src * 24 + lane]; }
    __syncwarp();

#pragma unroll
    for (int half = 0; half < 2; half++) {
        int idx = lane + half * 32;
        int c = idx >> 3, d = idx & 7;
        float dx = ctb[c * 3 + 0] - csb[d * 3 + 0];
        float dy = ctb[c * 3 + 1] - csb[d * 3 + 1];
        float dz = ctb[c * 3 + 2] - csb[d * 3 + 2];
        float ns = dx * dx + dy * dy + dz * dz;
        float nrm = (ns > 0.f) ? ns * rsqrtf(ns) : 0.f;
        Mm[idx] = nrm * inv_g * cwt[c] * cws[d];
    }
    __syncwarp();

#pragma unroll
    for (int half = 0; half < 2; half++) {
        int idx = lane + half * 32;
        int a = idx >> 3, d = idx & 7;
        float t = 0.f;
#pragma unroll
        for (int c = 0; c < 8; c++) t = fmaf(At[c * 8 + a], Mm[c * 8 + d], t);
        Tt[idx] = t;
    }
    __syncwarp();

    float r0 = 0.f, r1 = 0.f;
    {
        int a = lane >> 3, b = lane & 7;
#pragma unroll
        for (int d = 0; d < 8; d++) r0 = fmaf(Tt[a * 8 + d], Bs[d * 8 + b], r0);
        int idx = lane + 32;
        a = idx >> 3; b = idx & 7;
#pragma unroll
        for (int d = 0; d < 8; d++) r1 = fmaf(Tt[a * 8 + d], Bs[d * 8 + b], r1);
    }
    float ss = r0 * r0 + r1 * r1;
#pragma unroll
    for (int o = 16; o > 0; o >>= 1) ss += __shfl_xor_sync(0xffffffffu, ss, o);
    float invn = 1.f / (sqrtf(ss) + 0.001f);
    Mm[lane] = r0;
    Mm[lane + 32] = r1;
    __syncwarp();

    if (lane < 8) {
        float acc = 0.f;
#pragma unroll
        for (int k = 0; k < 64; k++) acc = fmaf(Mm[k], rl_w[k * 8 + lane], acc);
        g_rad[ge * 8 + lane] = acc * invn + rl_b[lane];
    }
    if (lane < 24) {
        int k = lane % 3;
        g_cdiff[ge * 24 + lane] = ctb[lane] - g_pcol[(long)src * 3 + k];
    }
    if (lane == 0) {
        int cs = g_csum[tgt];
        int ts = cs - 1;
        ts = ts < 0 ? 0 : (ts > 7 ? 7 : ts);
        g_meta[ge] = make_int4(tgt, src, ts, __float_as_int(edge_weights[ge]));
        g_wr[ge] = w_r[rel];
    }
}

// ---------------- fused edge GEMM kernel: bf16 MMA ----------------
struct __align__(128) EdgeSmem {
    bf16  ms1b[TILE_E * MSB];  // m1 (bf16, GEMM2 input)
    bf16  ms2b[TILE_E * MSB];  // m   (bf16, GEMM3 input)
    float ms2[TILE_E * MS];    // m   (fp32, for node_agg atomics)
    float cf[TILE_E * MS];     // cf  (fp32, for ef FFMA2 loop)
    float w1c[8 * 128];        // m_w1 rows 256..263 (radial part)
    float b1s[128];
    float b2s[128];
    float cb1s[128];
    float rad[TILE_E * 8];
    float ef[TILE_E * 8];
    int   s_tgt[TILE_E];
    int   s_src[TILE_E];
    float s_ew[TILE_E];
    float s_wr[TILE_E];
    int   s_ts[TILE_E];
};

__global__ __launch_bounds__(NTHR, 3)
void edge_kernel(const float* __restrict__ m_w1,
                 const float* __restrict__ m_b1,
                 const float* __restrict__ m_b2,
                 const float* __restrict__ c_b1) {
    extern __shared__ char smem_raw[];
    EdgeSmem& sm = *reinterpret_cast<EdgeSmem*>(smem_raw);

    const int tid = threadIdx.x;
    const long tileBase = (long)blockIdx.x * TILE_E;

    // stage W1c (radial rows) + biases
    for (int i = tid; i < 8 * 128; i += NTHR) sm.w1c[i] = m_w1[256 * 128 + i];
    if (tid < 128) {
        sm.b1s[tid]  = m_b1[tid];
        sm.b2s[tid]  = m_b2[tid];
        sm.cb1s[tid] = c_b1[tid];
    }

    // load meta + rad (coalesced)
    if (tid < TILE_E) {
        long ge = tileBase + tid;
        int4 m = g_meta[ge];
        sm.s_tgt[tid] = m.x;
        sm.s_src[tid] = m.y;
        sm.s_ts[tid]  = m.z;
        sm.s_ew[tid]  = __int_as_float(m.w);
        sm.s_wr[tid]  = g_wr[ge];
    }
    if (tid < TILE_E * 8)
        sm.rad[tid] = g_rad[tileBase * 8 + tid];
    __syncthreads();

    // ---- m1 = silu(Ah[tgt] + Bh[src] + rad @ W1c + b1) -> ms1b (bf16) ----
    {
        const int e = tid >> 3;          // 32 edges
        const int q = tid & 7;           // 8 col-quarters of 16
        const int j0 = q * 16;
        int t = sm.s_tgt[e];
        int s = sm.s_src[e];
        float r[8];
#pragma unroll
        for (int k = 0; k < 8; k++) r[k] = sm.rad[e * 8 + k];
#pragma unroll
        for (int v = 0; v < 4; v++) {
            int j = j0 + v * 4;
            float4 a  = *(const float4*)&g_Ah[(long)t * 128 + j];
            float4 b  = *(const float4*)&g_Bh[(long)s * 128 + j];
            float4 bb = *(const float4*)&sm.b1s[j];
            float4 acc;
            acc.x = a.x + b.x + bb.x;
            acc.y = a.y + b.y + bb.y;
            acc.z = a.z + b.z + bb.z;
            acc.w = a.w + b.w + bb.w;
#pragma unroll
            for (int k = 0; k < 8; k++) {
                float4 w = *(const float4*)&sm.w1c[k * 128 + j];
                acc.x = fmaf(r[k], w.x, acc.x);
                acc.y = fmaf(r[k], w.y, acc.y);
                acc.z = fmaf(r[k], w.z, acc.z);
                acc.w = fmaf(r[k], w.w, acc.w);
            }
            *(ull*)&sm.ms1b[e * MSB + j] =
                pack_bf16x4(silu_f(acc.x), silu_f(acc.y), silu_f(acc.z), silu_f(acc.w));
        }
    }
    __syncthreads();

    // ---- GEMM2 (bf16 MMA, fused bias+silu, dual fp32+bf16 output) ----
    wmma_bf16_32<2>(sm.ms1b, MSB, g_W2b, sm.ms2, MS, sm.ms2b, MSB, sm.b2s, tid);
    __syncthreads();

    // ---- GEMM3 (bf16 MMA, fused bias+silu, fp32 output) ----
    wmma_bf16_32<1>(sm.ms2b, MSB, g_CW1b, sm.cf, MS, nullptr, 0, sm.cb1s, tid);
    __syncthreads();

    // ---- edge_feat = cf @ c_w2  (32 edges x 8), packed-K FFMA2 ----
    {
        int e = tid >> 3;
        int j = tid & 7;
        ull acc = 0ull;
#pragma unroll 8
        for (int kp = 0; kp < 64; kp++) {
            ull cf = *(const ull*)&sm.cf[e * MS + kp * 2];
            FMA2(acc, cf, g_CW2p[kp * 8 + j], acc);
        }
        sm.ef[e * 8 + j] = lo_f(acc) + hi_f(acc);
    }
    __syncthreads();

    // ---- aggregation atomics ----
    for (int idx = tid; idx < TILE_E * 128; idx += NTHR) {
        int e = idx >> 7, j = idx & 127;
        int t = sm.s_tgt[e];
        atomicAdd(&g_node_agg[(long)t * 128 + j], sm.ms2[e * MS + j] * sm.s_ew[e]);
    }
    if (tid < TILE_E * 8) {
        int e = tid >> 3, a = tid & 7;
        int t = sm.s_tgt[e];
        int ts = sm.s_ts[e];
        int w = 8 - ts;
        int hi = a + w; if (hi > 8) hi = 8;
        float s = 0.f;
        for (int b = a; b < hi; b++) s += sm.ef[e * 8 + b];
        float pe = (s / (float)w) * sm.s_wr[e];
        long ge = tileBase + e;
#pragma unroll
        for (int k = 0; k < 3; k++)
            atomicAdd(&g_coord_sum[(long)t * 24 + a * 3 + k],
                      g_cdiff[ge * 24 + a * 3 + k] * pe);
    }
    if (tid < TILE_E) {
        atomicAdd(&g_cnt[sm.s_tgt[tid]], 1.f);
    }
}

// ---------------- node epilogue: bf16 het GEMM + BN + silu + residuals ----------------
__global__ __launch_bounds__(NTHR, 3)
void node_out_kernel(const float* __restrict__ h,
                     const float* __restrict__ coords,
                     const float* __restrict__ het_b,
                     const float* __restrict__ gamma,
                     const float* __restrict__ beta,
                     float* __restrict__ out) {
    __shared__ __align__(128) bf16  agb[32 * MSB];
    __shared__ __align__(128) float og[32 * MS];
    const int tid = threadIdx.x;
    const int base = blockIdx.x * 32;
    const float INVS = 0.9999950000374996f;  // 1/sqrt(1+1e-5)

    for (int idx = tid; idx < 32 * 128; idx += NTHR) {
        int n = idx >> 7, k = idx & 127;
        int gn = base + n;
        agb[n * MSB + k] = __float2bfloat16_rn((gn < NN) ? g_node_agg[(long)gn * 128 + k] : 0.f);
    }
    __syncthreads();

    wmma_bf16_32<0>(agb, MSB, g_HWb, og, MS, nullptr, 0, nullptr, tid);
    __syncthreads();

    for (int idx = tid; idx < 32 * 32; idx += NTHR) {
        int n = idx >> 5, jq = idx & 31;
        int j = jq * 4;
        int gn = base + n;
        if (gn < NN) {
            float4 v  = *(const float4*)&og[n * MS + j];
            float4 hb = *(const float4*)&het_b[j];
            float4 gm = *(const float4*)&gamma[j];
            float4 bt = *(const float4*)&beta[j];
            float4 hv = *(const float4*)&h[(long)gn * 128 + j];
            float4 o;
            o.x = silu_f((v.x + hb.x) * INVS * gm.x + bt.x) + hv.x;
            o.y = silu_f((v.y + hb.y) * INVS * gm.y + bt.y) + hv.y;
            o.z = silu_f((v.z + hb.z) * INVS * gm.z + bt.z) + hv.z;
            o.w = silu_f((v.w + hb.w) * INVS * gm.w + bt.w) + hv.w;
            *(float4*)&out[(long)gn * 128 + j] = o;
        }
    }

    for (int idx = tid; idx < 32 * 24; idx += NTHR) {
        int n = idx / 24, k = idx % 24;
        int gn = base + n;
        if (gn < NN) {
            float c = fmaxf(g_cnt[gn], 1.f);
            out[(long)NN * 128 + (long)gn * 24 + k] =
                coords[(long)gn * 24 + k] + g_coord_sum[(long)gn * 24 + k] / c;
        }
    }
}

// ---------------- launch ----------------
extern "C" void kernel_launch(void* const* d_in, const int* in_sizes, int n_in,
                              void* d_out, int out_size) {
    (void)in_sizes; (void)n_in; (void)out_size;
    const float* h      = (const float*)d_in[0];
    const float* coords = (const float*)d_in[1];
    const float* ca     = (const float*)d_in[2];
    const float* cw     = (const float*)d_in[3];
    const float* ew     = (const float*)d_in[4];
    const int*   el     = (const int*)d_in[5];
    const float* rl_w   = (const float*)d_in[6];
    const float* rl_b   = (const float*)d_in[7];
    const float* m_w1   = (const float*)d_in[8];
    const float* m_b1   = (const float*)d_in[9];
    const float* m_w2   = (const float*)d_in[10];
    const float* m_b2   = (const float*)d_in[11];
    const float* c_w1   = (const float*)d_in[12];
    const float* c_b1   = (const float*)d_in[13];
    const float* c_w2   = (const float*)d_in[14];
    const float* het_w  = (const float*)d_in[15];
    const float* het_b  = (const float*)d_in[16];
    const float* gamma  = (const float*)d_in[17];
    const float* beta   = (const float*)d_in[18];
    const float* w_r    = (const float*)d_in[19];
    float* out = (float*)d_out;

    cudaFuncSetAttribute(edge_kernel, cudaFuncAttributeMaxDynamicSharedMemorySize,
                         (int)sizeof(EdgeSmem));

    zero_kernel<<<2048, 256>>>();
    pack_kernel<<<256, 256>>>(m_w1, m_w2, c_w1, c_w2, het_w);
    node_pre_kernel<<<(NN + 255) / 256, 256>>>(coords, cw);
    node_gemm_kernel<<<(NN + 63) / 64, NTHR>>>(h);
    max_kernel<<<(EE + 255) / 256, 256>>>(coords, el);
    edge_pre_kernel<<<(EE + 7) / 8, 256>>>(coords, ca, cw, ew, el, rl_w, rl_b, w_r);
    edge_kernel<<<EE / TILE_E, NTHR, sizeof(EdgeSmem)>>>(m_w1, m_b1, m_b2, c_b1);
    node_out_kernel<<<(NN + 31) / 32, NTHR>>>(h, coords, het_b, gamma, beta, out);
}

// round 16
// speedup vs baseline: 1.4175x; 1.2866x over previous
#include <cuda_runtime.h>
#include <cuda_bf16.h>
#include <mma.h>
#include <math.h>

using namespace nvcuda;

#define NN 50000
#define EE 400000
#define DD 128
#define CC 8

#define TILE_E 32
#define NTHR 256
#define MS 132    // fp32 row stride (16B-aligned rows)
#define MSB 136   // bf16 row stride (272 B = multiple of 16 B)

typedef unsigned long long ull;
typedef __nv_bfloat16 bf16;

// ---------------- device scratch (no allocations allowed) ----------------
__device__ float g_node_agg[NN * DD];
__device__ float g_coord_sum[NN * CC * 3];
__device__ float g_cnt[NN];
__device__ float g_pcol[NN * 3];
__device__ int   g_csum[NN];
__device__ unsigned int g_maxbits;
__device__ float g_Ah[(NN + 64) * DD];   // +64 rows padding for wmma tile overrun
__device__ float g_Bh[(NN + 64) * DD];

// edge-pre outputs
__device__ float g_rad[EE * 8];
__device__ float g_cdiff[EE * 24];
__device__ int4  g_meta[EE];
__device__ float g_wr[EE];

// bf16 weights in FRAGMENT-TILED layout: tile (kt, nt) contiguous 256 elems,
// index = (kt*8 + nt)*256 + r*16 + c.  Fragment load: ptr = base + tile*256, ld = 16.
__device__ bf16 g_W1bt[2 * 64 * 256];   // m_w1 rows 0..255 (two 128x128 halves)
__device__ bf16 g_W2bt[64 * 256];       // m_w2
__device__ bf16 g_CW1bt[64 * 256];      // c_w1
__device__ bf16 g_HWbt[64 * 256];       // het_w

// packed fp32 weights for the small FFMA2 path
__device__ ull g_CW2p[64 * 8];          // c_w2

__device__ __forceinline__ float silu_f(float x) {
    return x * (1.0f / (1.0f + __expf(-x)));
}
__device__ __forceinline__ ull packf2(float lo, float hi) {
    return ((ull)__float_as_uint(hi) << 32) | (ull)__float_as_uint(lo);
}
__device__ __forceinline__ float lo_f(ull p) { return __uint_as_float((unsigned)(p & 0xffffffffull)); }
__device__ __forceinline__ float hi_f(ull p) { return __uint_as_float((unsigned)(p >> 32)); }

__device__ __forceinline__ ull pack_bf16x4(float a, float b, float c, float d) {
    unsigned short h0 = __bfloat16_as_ushort(__float2bfloat16_rn(a));
    unsigned short h1 = __bfloat16_as_ushort(__float2bfloat16_rn(b));
    unsigned short h2 = __bfloat16_as_ushort(__float2bfloat16_rn(c));
    unsigned short h3 = __bfloat16_as_ushort(__float2bfloat16_rn(d));
    return ((ull)h3 << 48) | ((ull)h2 << 32) | ((ull)h1 << 16) | (ull)h0;
}

#define FMA2(d, a, b, c) asm("fma.rn.f32x2 %0, %1, %2, %3;" : "=l"(d) : "l"(a), "l"(b), "l"(c))

// ---------------- bf16 wmma helpers (tiled-B) ----------------
// 32-row: dst(32x128 fp32, ds) = src(32x128 bf16, ss) @ Wt(fragment-tiled 128x128)
// EPI: 0 = raw store; 1 = fused warp-local bias+silu; 2 = bias+silu + bf16 copy
template <int EPI>
__device__ __forceinline__ void wmma_bf16_32(const bf16* __restrict__ src, int ss,
                                             const bf16* __restrict__ Wt,
                                             float* __restrict__ dst, int ds,
                                             bf16* __restrict__ dstb, int dsb,
                                             const float* __restrict__ bias,
                                             int tid) {
    const int w   = tid >> 5;
    const int mt  = w & 1;
    const int nt0 = (w >> 1) * 2;

    wmma::fragment<wmma::accumulator, 16, 16, 16, float> c0, c1;
    wmma::fill_fragment(c0, 0.f);
    wmma::fill_fragment(c1, 0.f);

#pragma unroll
    for (int k = 0; k < 8; k++) {
        wmma::fragment<wmma::matrix_a, 16, 16, 16, bf16, wmma::row_major> fa;
        wmma::fragment<wmma::matrix_b, 16, 16, 16, bf16, wmma::row_major> fb0, fb1;
        wmma::load_matrix_sync(fa, src + (mt * 16) * ss + k * 16, ss);
        wmma::load_matrix_sync(fb0, Wt + (k * 8 + nt0) * 256, 16);
        wmma::load_matrix_sync(fb1, Wt + (k * 8 + nt0 + 1) * 256, 16);
        wmma::mma_sync(c0, fa, fb0, c0);
        wmma::mma_sync(c1, fa, fb1, c1);
    }
    wmma::store_matrix_sync(dst + (mt * 16) * ds + nt0 * 16, c0, ds, wmma::mem_row_major);
    wmma::store_matrix_sync(dst + (mt * 16) * ds + (nt0 + 1) * 16, c1, ds, wmma::mem_row_major);

    if (EPI >= 1) {
        __syncwarp();
        const int lane = tid & 31;
        int row = mt * 16 + (lane & 15);
        int col0 = nt0 * 16 + (lane >> 4) * 16;
        float* p = dst + row * ds;
#pragma unroll
        for (int v = 0; v < 4; v++) {
            int j = col0 + v * 4;
            float4 x  = *(const float4*)&p[j];
            float4 bb = *(const float4*)&bias[j];
            x.x = silu_f(x.x + bb.x);
            x.y = silu_f(x.y + bb.y);
            x.z = silu_f(x.z + bb.z);
            x.w = silu_f(x.w + bb.w);
            *(float4*)&p[j] = x;
            if (EPI == 2)
                *(ull*)&dstb[row * dsb + j] = pack_bf16x4(x.x, x.y, x.z, x.w);
        }
    }
}

// 64-row: dst(64x128 fp32, ds) = src(64x128 bf16, ss) @ Wt(fragment-tiled)
__device__ __forceinline__ void wmma_bf16_64(const bf16* __restrict__ src, int ss,
                                             const bf16* __restrict__ Wt,
                                             float* __restrict__ dst, int ds,
                                             int tid) {
    const int w   = tid >> 5;
    const int mt  = w & 3;
    const int nt0 = (w >> 2) * 4;

    wmma::fragment<wmma::accumulator, 16, 16, 16, float> c[4];
#pragma unroll
    for (int j = 0; j < 4; j++) wmma::fill_fragment(c[j], 0.f);

#pragma unroll
    for (int k = 0; k < 8; k++) {
        wmma::fragment<wmma::matrix_a, 16, 16, 16, bf16, wmma::row_major> fa;
        wmma::load_matrix_sync(fa, src + (mt * 16) * ss + k * 16, ss);
#pragma unroll
        for (int j = 0; j < 4; j++) {
            wmma::fragment<wmma::matrix_b, 16, 16, 16, bf16, wmma::row_major> fb;
            wmma::load_matrix_sync(fb, Wt + (k * 8 + nt0 + j) * 256, 16);
            wmma::mma_sync(c[j], fa, fb, c[j]);
        }
    }
#pragma unroll
    for (int j = 0; j < 4; j++)
        wmma::store_matrix_sync(dst + (mt * 16) * ds + (nt0 + j) * 16, c[j], ds, wmma::mem_row_major);
}

// ---------------- zero scratch ----------------
__global__ void zero_kernel() {
    long t0 = (long)blockIdx.x * blockDim.x + threadIdx.x;
    long stride = (long)gridDim.x * blockDim.x;
    for (long i = t0; i < (long)NN * DD; i += stride) g_node_agg[i] = 0.f;
    for (long i = t0; i < (long)NN * 24; i += stride) g_coord_sum[i] = 0.f;
    for (long i = t0; i < NN; i += stride) g_cnt[i] = 0.f;
    if (t0 == 0) g_maxbits = 0u;
}

// ---------------- weight pre-packing: bf16 + fragment tiling ----------------
__global__ void pack_kernel(const float* __restrict__ m_w1,
                            const float* __restrict__ m_w2,
                            const float* __restrict__ c_w1,
                            const float* __restrict__ c_w2,
                            const float* __restrict__ het_w) {
    int t0 = blockIdx.x * blockDim.x + threadIdx.x;
    int stride = gridDim.x * blockDim.x;
    // tiled index for a 128x128 matrix: row, col -> (row>>4 * 8 + col>>4)*256 + (row&15)*16 + (col&15)
    for (int i = t0; i < 256 * 128; i += stride) {
        int row = i >> 7, col = i & 127;
        int half = row >> 7;           // 0 or 1
        int r = row & 127;
        int tidx = ((r >> 4) * 8 + (col >> 4)) * 256 + (r & 15) * 16 + (col & 15);
        g_W1bt[half * 64 * 256 + tidx] = __float2bfloat16_rn(m_w1[i]);
    }
    for (int i = t0; i < 128 * 128; i += stride) {
        int row = i >> 7, col = i & 127;
        int tidx = ((row >> 4) * 8 + (col >> 4)) * 256 + (row & 15) * 16 + (col & 15);
        g_W2bt[tidx]  = __float2bfloat16_rn(m_w2[i]);
        g_CW1bt[tidx] = __float2bfloat16_rn(c_w1[i]);
        g_HWbt[tidx]  = __float2bfloat16_rn(het_w[i]);
    }
    for (int i = t0; i < 64 * 8; i += stride) {
        int kp = i >> 3, j = i & 7;
        g_CW2p[i] = packf2(c_w2[(2 * kp) * 8 + j], c_w2[(2 * kp + 1) * 8 + j]);
    }
}

// ---------------- per-node precompute: csum, pooled_col ----------------
__global__ void node_pre_kernel(const float* __restrict__ coords,
                                const float* __restrict__ cw) {
    int n = blockIdx.x * blockDim.x + threadIdx.x;
    if (n >= NN) return;
    float px = 0.f, py = 0.f, pz = 0.f;
    int cs = 0;
#pragma unroll
    for (int c = 0; c < 8; c++) {
        float w = cw[n * 8 + c];
        if (w != 0.f) {
            cs++;
            px += coords[n * 24 + c * 3 + 0];
            py += coords[n * 24 + c * 3 + 1];
            pz += coords[n * 24 + c * 3 + 2];
        }
    }
    float inv = 1.f / ((float)cs + 0.001f);
    g_pcol[n * 3 + 0] = px * inv;
    g_pcol[n * 3 + 1] = py * inv;
    g_pcol[n * 3 + 2] = pz * inv;
    g_csum[n] = cs;
}

// ---------------- global max of squared channel distances ----------------
__global__ void max_kernel(const float* __restrict__ coords,
                           const int* __restrict__ el) {
    int e = blockIdx.x * blockDim.x + threadIdx.x;
    float m = 0.f;
    if (e < EE) {
        int src = el[e * 3 + 0];
        int tgt = el[e * 3 + 1];
        float ct[24], cs[24];
#pragma unroll
        for (int i = 0; i < 24; i++) {
            ct[i] = coords[(long)tgt * 24 + i];
            cs[i] = coords[(long)src * 24 + i];
        }
#pragma unroll
        for (int c = 0; c < 8; c++) {
#pragma unroll
            for (int d = 0; d < 8; d++) {
                float dx = ct[c * 3 + 0] - cs[d * 3 + 0];
                float dy = ct[c * 3 + 1] - cs[d * 3 + 1];
                float dz = ct[c * 3 + 2] - cs[d * 3 + 2];
                float ns = dx * dx + dy * dy + dz * dz;
                m = fmaxf(m, ns);
            }
        }
    }
#pragma unroll
    for (int o = 16; o > 0; o >>= 1)
        m = fmaxf(m, __shfl_xor_sync(0xffffffffu, m, o));
    if ((threadIdx.x & 31) == 0)
        atomicMax(&g_maxbits, __float_as_uint(m));
}

// ---------------- per-node GEMM via bf16 wmma (64-row tiles) ----------------
__global__ __launch_bounds__(NTHR, 3)
void node_gemm_kernel(const float* __restrict__ h) {
    __shared__ __align__(128) bf16 hs[64 * MSB];
    const int tid = threadIdx.x;
    const int base = blockIdx.x * 64;

    for (int idx = tid; idx < 64 * 128; idx += NTHR) {
        int n = idx >> 7, k = idx & 127;
        int gn = base + n;
        hs[n * MSB + k] = __float2bfloat16_rn((gn < NN) ? h[(long)gn * 128 + k] : 0.f);
    }
    __syncthreads();

    wmma_bf16_64(hs, MSB, g_W1bt,            &g_Ah[(long)base * 128], 128, tid);
    wmma_bf16_64(hs, MSB, g_W1bt + 64 * 256, &g_Bh[(long)base * 128], 128, tid);
}

// ---------------- edge preprocessing: one edge per warp (R6 version) ----------------
__global__ __launch_bounds__(256)
void edge_pre_kernel(const float* __restrict__ coords,
                     const float* __restrict__ ca,
                     const float* __restrict__ cw,
                     const float* __restrict__ edge_weights,
                     const int* __restrict__ el,
                     const float* __restrict__ rl_w,
                     const float* __restrict__ rl_b,
                     const float* __restrict__ w_r) {
    __shared__ float wscr[8][320];
    const int wid = threadIdx.x >> 5;
    const int lane = threadIdx.x & 31;
    const long ge = (long)blockIdx.x * 8 + wid;
    if (ge >= (long)EE) return;

    float gmax = sqrtf(__uint_as_float(g_maxbits));
    float inv_g = 1.f / (gmax + 0.001f);

    float* WS  = &wscr[wid][0];
    float* At  = WS;
    float* Bs  = WS + 64;
    float* Mm  = WS + 128;
    float* Tt  = WS + 192;
    float* cwt = WS + 256;
    float* cws = WS + 264;
    float* ctb = WS + 272;
    float* csb = WS + 296;

    int src = el[ge * 3 + 0];
    int tgt = el[ge * 3 + 1];
    int rel = el[ge * 3 + 2];

    At[lane]      = ca[(long)tgt * 64 + lane];
    At[lane + 32] = ca[(long)tgt * 64 + lane + 32];
    Bs[lane]      = ca[(long)src * 64 + lane];
    Bs[lane + 32] = ca[(long)src * 64 + lane + 32];
    if (lane < 8) { cwt[lane] = cw[(long)tgt * 8 + lane]; cws[lane] = cw[(long)src * 8 + lane]; }
    if (lane < 24) { ctb[lane] = coords[(long)tgt * 24 + lane]; csb[lane] = coords[(long)src * 24 + lane]; }
    __syncwarp();

#pragma unroll
    for (int half = 0; half < 2; half++) {
        int idx = lane + half * 32;
        int c = idx >> 3, d = idx & 7;
        float dx = ctb[c * 3 + 0] - csb[d * 3 + 0];
        float dy = ctb[c * 3 + 1] - csb[d * 3 + 1];
        float dz = ctb[c * 3 + 2] - csb[d * 3 + 2];
        float ns = dx * dx + dy * dy + dz * dz;
        float nrm = (ns > 0.f) ? ns * rsqrtf(ns) : 0.f;
        Mm[idx] = nrm * inv_g * cwt[c] * cws[d];
    }
    __syncwarp();

#pragma unroll
    for (int half = 0; half < 2; half++) {
        int idx = lane + half * 32;
        int a = idx >> 3, d = idx & 7;
        float t = 0.f;
#pragma unroll
        for (int c = 0; c < 8; c++) t = fmaf(At[c * 8 + a], Mm[c * 8 + d], t);
        Tt[idx] = t;
    }
    __syncwarp();

    float r0 = 0.f, r1 = 0.f;
    {
        int a = lane >> 3, b = lane & 7;
#pragma unroll
        for (int d = 0; d < 8; d++) r0 = fmaf(Tt[a * 8 + d], Bs[d * 8 + b], r0);
        int idx = lane + 32;
        a = idx >> 3; b = idx & 7;
#pragma unroll
        for (int d = 0; d < 8; d++) r1 = fmaf(Tt[a * 8 + d], Bs[d * 8 + b], r1);
    }
    float ss = r0 * r0 + r1 * r1;
#pragma unroll
    for (int o = 16; o > 0; o >>= 1) ss += __shfl_xor_sync(0xffffffffu, ss, o);
    float invn = 1.f / (sqrtf(ss) + 0.001f);
    Mm[lane] = r0;
    Mm[lane + 32] = r1;
    __syncwarp();

    if (lane < 8) {
        float acc = 0.f;
#pragma unroll
        for (int k = 0; k < 64; k++) acc = fmaf(Mm[k], rl_w[k * 8 + lane], acc);
        g_rad[ge * 8 + lane] = acc * invn + rl_b[lane];
    }
    if (lane < 24) {
        int k = lane % 3;
        g_cdiff[ge * 24 + lane] = ctb[lane] - g_pcol[(long)src * 3 + k];
    }
    if (lane == 0) {
        int cs = g_csum[tgt];
        int ts = cs - 1;
        ts = ts < 0 ? 0 : (ts > 7 ? 7 : ts);
        g_meta[ge] = make_int4(tgt, src, ts, __float_as_int(edge_weights[ge]));
        g_wr[ge] = w_r[rel];
    }
}

// ---------------- fused edge GEMM kernel: bf16 MMA, tiled weights ----------------
struct __align__(128) EdgeSmem {
    bf16  ms1b[TILE_E * MSB];  // m1 (bf16, GEMM2 input)
    bf16  ms2b[TILE_E * MSB];  // m   (bf16, GEMM3 input)
    float ms2[TILE_E * MS];    // m   (fp32, for node_agg atomics)
    float cf[TILE_E * MS];     // cf  (fp32, for ef FFMA2 loop)
    float w1c[8 * 128];        // m_w1 rows 256..263 (radial part)
    float b1s[128];
    float b2s[128];
    float cb1s[128];
    float rad[TILE_E * 8];
    float ef[TILE_E * 8];
    int   s_tgt[TILE_E];
    int   s_src[TILE_E];
    float s_ew[TILE_E];
    float s_wr[TILE_E];
    int   s_ts[TILE_E];
};

__global__ __launch_bounds__(NTHR, 3)
void edge_kernel(const float* __restrict__ m_w1,
                 const float* __restrict__ m_b1,
                 const float* __restrict__ m_b2,
                 const float* __restrict__ c_b1) {
    extern __shared__ char smem_raw[];
    EdgeSmem& sm = *reinterpret_cast<EdgeSmem*>(smem_raw);

    const int tid = threadIdx.x;
    const long tileBase = (long)blockIdx.x * TILE_E;

    // stage W1c (radial rows) + biases
    for (int i = tid; i < 8 * 128; i += NTHR) sm.w1c[i] = m_w1[256 * 128 + i];
    if (tid < 128) {
        sm.b1s[tid]  = m_b1[tid];
        sm.b2s[tid]  = m_b2[tid];
        sm.cb1s[tid] = c_b1[tid];
    }

    // load meta + rad (coalesced)
    if (tid < TILE_E) {
        long ge = tileBase + tid;
        int4 m = g_meta[ge];
        sm.s_tgt[tid] = m.x;
        sm.s_src[tid] = m.y;
        sm.s_ts[tid]  = m.z;
        sm.s_ew[tid]  = __int_as_float(m.w);
        sm.s_wr[tid]  = g_wr[ge];
    }
    if (tid < TILE_E * 8)
        sm.rad[tid] = g_rad[tileBase * 8 + tid];
    __syncthreads();

    // ---- m1 = silu(Ah[tgt] + Bh[src] + rad @ W1c + b1) -> ms1b (bf16) ----
    {
        const int e = tid >> 3;          // 32 edges
        const int q = tid & 7;           // 8 col-quarters of 16
        const int j0 = q * 16;
        int t = sm.s_tgt[e];
        int s = sm.s_src[e];
        float r[8];
#pragma unroll
        for (int k = 0; k < 8; k++) r[k] = sm.rad[e * 8 + k];
#pragma unroll
        for (int v = 0; v < 4; v++) {
            int j = j0 + v * 4;
            float4 a  = *(const float4*)&g_Ah[(long)t * 128 + j];
            float4 b  = *(const float4*)&g_Bh[(long)s * 128 + j];
            float4 bb = *(const float4*)&sm.b1s[j];
            float4 acc;
            acc.x = a.x + b.x + bb.x;
            acc.y = a.y + b.y + bb.y;
            acc.z = a.z + b.z + bb.z;
            acc.w = a.w + b.w + bb.w;
#pragma unroll
            for (int k = 0; k < 8; k++) {
                float4 w = *(const float4*)&sm.w1c[k * 128 + j];
                acc.x = fmaf(r[k], w.x, acc.x);
                acc.y = fmaf(r[k], w.y, acc.y);
                acc.z = fmaf(r[k], w.z, acc.z);
                acc.w = fmaf(r[k], w.w, acc.w);
            }
            *(ull*)&sm.ms1b[e * MSB + j] =
                pack_bf16x4(silu_f(acc.x), silu_f(acc.y), silu_f(acc.z), silu_f(acc.w));
        }
    }
    __syncthreads();

    // ---- GEMM2 (bf16 MMA, fused bias+silu, dual fp32+bf16 output) ----
    wmma_bf16_32<2>(sm.ms1b, MSB, g_W2bt, sm.ms2, MS, sm.ms2b, MSB, sm.b2s, tid);
    __syncthreads();

    // ---- GEMM3 (bf16 MMA, fused bias+silu, fp32 output) ----
    wmma_bf16_32<1>(sm.ms2b, MSB, g_CW1bt, sm.cf, MS, nullptr, 0, sm.cb1s, tid);
    __syncthreads();

    // ---- edge_feat = cf @ c_w2  (32 edges x 8), packed-K FFMA2 ----
    {
        int e = tid >> 3;
        int j = tid & 7;
        ull acc = 0ull;
#pragma unroll 8
        for (int kp = 0; kp < 64; kp++) {
            ull cf = *(const ull*)&sm.cf[e * MS + kp * 2];
            FMA2(acc, cf, g_CW2p[kp * 8 + j], acc);
        }
        sm.ef[e * 8 + j] = lo_f(acc) + hi_f(acc);
    }
    __syncthreads();

    // ---- aggregation atomics ----
    for (int idx = tid; idx < TILE_E * 128; idx += NTHR) {
        int e = idx >> 7, j = idx & 127;
        int t = sm.s_tgt[e];
        atomicAdd(&g_node_agg[(long)t * 128 + j], sm.ms2[e * MS + j] * sm.s_ew[e]);
    }
    if (tid < TILE_E * 8) {
        int e = tid >> 3, a = tid & 7;
        int t = sm.s_tgt[e];
        int ts = sm.s_ts[e];
        int w = 8 - ts;
        int hi = a + w; if (hi > 8) hi = 8;
        float s = 0.f;
        for (int b = a; b < hi; b++) s += sm.ef[e * 8 + b];
        float pe = (s / (float)w) * sm.s_wr[e];
        long ge = tileBase + e;
#pragma unroll
        for (int k = 0; k < 3; k++)
            atomicAdd(&g_coord_sum[(long)t * 24 + a * 3 + k],
                      g_cdiff[ge * 24 + a * 3 + k] * pe);
    }
    if (tid < TILE_E) {
        atomicAdd(&g_cnt[sm.s_tgt[tid]], 1.f);
    }
}

// ---------------- node epilogue: bf16 het GEMM + BN + silu + residuals ----------------
__global__ __launch_bounds__(NTHR, 3)
void node_out_kernel(const float* __restrict__ h,
                     const float* __restrict__ coords,
                     const float* __restrict__ het_b,
                     const float* __restrict__ gamma,
                     const float* __restrict__ beta,
                     float* __restrict__ out) {
    __shared__ __align__(128) bf16  agb[32 * MSB];
    __shared__ __align__(128) float og[32 * MS];
    const int tid = threadIdx.x;
    const int base = blockIdx.x * 32;
    const float INVS = 0.9999950000374996f;  // 1/sqrt(1+1e-5)

    for (int idx = tid; idx < 32 * 128; idx += NTHR) {
        int n = idx >> 7, k = idx & 127;
        int gn = base + n;
        agb[n * MSB + k] = __float2bfloat16_rn((gn < NN) ? g_node_agg[(long)gn * 128 + k] : 0.f);
    }
    __syncthreads();

    wmma_bf16_32<0>(agb, MSB, g_HWbt, og, MS, nullptr, 0, nullptr, tid);
    __syncthreads();

    for (int idx = tid; idx < 32 * 32; idx += NTHR) {
        int n = idx >> 5, jq = idx & 31;
        int j = jq * 4;
        int gn = base + n;
        if (gn < NN) {
            float4 v  = *(const float4*)&og[n * MS + j];
            float4 hb = *(const float4*)&het_b[j];
            float4 gm = *(const float4*)&gamma[j];
            float4 bt = *(const float4*)&beta[j];
            float4 hv = *(const float4*)&h[(long)gn * 128 + j];
            float4 o;
            o.x = silu_f((v.x + hb.x) * INVS * gm.x + bt.x) + hv.x;
            o.y = silu_f((v.y + hb.y) * INVS * gm.y + bt.y) + hv.y;
            o.z = silu_f((v.z + hb.z) * INVS * gm.z + bt.z) + hv.z;
            o.w = silu_f((v.w + hb.w) * INVS * gm.w + bt.w) + hv.w;
            *(float4*)&out[(long)gn * 128 + j] = o;
        }
    }

    for (int idx = tid; idx < 32 * 24; idx += NTHR) {
        int n = idx / 24, k = idx % 24;
        int gn = base + n;
        if (gn < NN) {
            float c = fmaxf(g_cnt[gn], 1.f);
            out[(long)NN * 128 + (long)gn * 24 + k] =
                coords[(long)gn * 24 + k] + g_coord_sum[(long)gn * 24 + k] / c;
        }
    }
}

// ---------------- launch ----------------
extern "C" void kernel_launch(void* const* d_in, const int* in_sizes, int n_in,
                              void* d_out, int out_size) {
    (void)in_sizes; (void)n_in; (void)out_size;
    const float* h      = (const float*)d_in[0];
    const float* coords = (const float*)d_in[1];
    const float* ca     = (const float*)d_in[2];
    const float* cw     = (const float*)d_in[3];
    const float* ew     = (const float*)d_in[4];
    const int*   el     = (const int*)d_in[5];
    const float* rl_w   = (const float*)d_in[6];
    const float* rl_b   = (const float*)d_in[7];
    const float* m_w1   = (const float*)d_in[8];
    const float* m_b1   = (const float*)d_in[9];
    const float* m_w2   = (const float*)d_in[10];
    const float* m_b2   = (const float*)d_in[11];
    const float* c_w1   = (const float*)d_in[12];
    const float* c_b1   = (const float*)d_in[13];
    const float* c_w2   = (const float*)d_in[14];
    const float* het_w  = (const float*)d_in[15];
    const float* het_b  = (const float*)d_in[16];
    const float* gamma  = (const float*)d_in[17];
    const float* beta   = (const float*)d_in[18];
    const float* w_r    = (const float*)d_in[19];
    float* out = (float*)d_out;

    cudaFuncSetAttribute(edge_kernel, cudaFuncAttributeMaxDynamicSharedMemorySize,
                         (int)sizeof(EdgeSmem));

    zero_kernel<<<2048, 256>>>();
    pack_kernel<<<256, 256>>>(m_w1, m_w2, c_w1, c_w2, het_w);
    node_pre_kernel<<<(NN + 255) / 256, 256>>>(coords, cw);
    node_gemm_kernel<<<(NN + 63) / 64, NTHR>>>(h);
    max_kernel<<<(EE + 255) / 256, 256>>>(coords, el);
    edge_pre_kernel<<<(EE + 7) / 8, 256>>>(coords, ca, cw, ew, el, rl_w, rl_b, w_r);
    edge_kernel<<<EE / TILE_E, NTHR, sizeof(EdgeSmem)>>>(m_w1, m_b1, m_b2, c_b1);
    node_out_kernel<<<(NN + 31) / 32, NTHR>>>(h, coords, het_b, gamma, beta, out);
}